// round 8
// baseline (speedup 1.0000x reference)
#include <cuda_runtime.h>
#include <cuda_fp16.h>
#include <cstdint>

#define NPIX 9216
#define HH 96
#define CC 21
#define NB 24
#define CRF_ITERS 5
#define APP_W 10.0f
#define SMO_W 3.0f

#define NBLK 144                        // 64-pixel blocks
#define NTILE (NBLK * (NBLK + 1) / 2)   // 10440 stored upper-tri tiles
#define NSTEP 36                        // 2 J-blocks per step, split-K x2

// smem stage layout (bytes): 2 A-tiles (hi only) + 2 P-tiles (hi+lo)
#define A0OF 0
#define A1OF 8192
#define P0HI 16384
#define P0LO 19456
#define P1HI 22528
#define P1LO 25600
#define STAGEB 28672
#define NSTAGE 3
#define GEMM_SMEM (NSTAGE * STAGEB)     // 86016
#define FULLB 28672

// XOR swizzle baked into gmem tile layout
#define SW(off) ((off) ^ ((((off) >> 7) & 7) << 4))

// ---------------- persistent device scratch ----------------
static __device__ __half g_Khi[(size_t)NTILE * 4096];  // 85.5 MB, tile-contiguous
static __device__ float  g_feat[6 * NPIX];
static __device__ float  g_gauss[HH];
static __device__ float  g_unary[CC * NPIX];
static __device__ __half g_Bhi[NBLK * NB * 64];        // [block][class][64], swizzled
static __device__ __half g_Blo[NBLK * NB * 64];
static __device__ float  g_part[2][(size_t)NPIX * NB];
static __device__ float  g_smo[CC * NPIX];

// ---------------- PTX helpers ----------------
__device__ __forceinline__ uint32_t smem_u32(const void* p) {
    uint32_t a;
    asm("{ .reg .u64 t; cvta.to.shared.u64 t, %1; cvt.u32.u64 %0, t; }" : "=r"(a) : "l"(p));
    return a;
}
__device__ __forceinline__ void mbar_init(uint32_t a, uint32_t c) {
    asm volatile("mbarrier.init.shared.b64 [%0], %1;" :: "r"(a), "r"(c) : "memory");
}
__device__ __forceinline__ void mbar_expect_tx(uint32_t a, uint32_t bytes) {
    asm volatile("mbarrier.arrive.expect_tx.shared.b64 _, [%0], %1;" :: "r"(a), "r"(bytes) : "memory");
}
__device__ __forceinline__ void mbar_wait(uint32_t mbar, uint32_t parity) {
    asm volatile(
        "{\n\t.reg .pred P1;\n\t"
        "WL%=:\n\t"
        "mbarrier.try_wait.parity.shared.b64 P1, [%0], %1;\n\t"
        "@!P1 bra WL%=;\n\t}"
        :: "r"(mbar), "r"(parity) : "memory");
}
__device__ __forceinline__ void bulk_cp(uint32_t dst, const void* src, uint32_t bytes, uint32_t mbar) {
    asm volatile(
        "cp.async.bulk.shared::cluster.global.mbarrier::complete_tx::bytes [%0], [%1], %2, [%3];"
        :: "r"(dst), "l"(src), "r"(bytes), "r"(mbar) : "memory");
}
__device__ __forceinline__ void ldsm4(uint32_t& r0, uint32_t& r1, uint32_t& r2, uint32_t& r3, uint32_t addr) {
    asm volatile("ldmatrix.sync.aligned.m8n8.x4.shared.b16 {%0,%1,%2,%3}, [%4];"
        : "=r"(r0), "=r"(r1), "=r"(r2), "=r"(r3) : "r"(addr));
}
__device__ __forceinline__ void ldsm4t(uint32_t& r0, uint32_t& r1, uint32_t& r2, uint32_t& r3, uint32_t addr) {
    asm volatile("ldmatrix.sync.aligned.m8n8.x4.trans.shared.b16 {%0,%1,%2,%3}, [%4];"
        : "=r"(r0), "=r"(r1), "=r"(r2), "=r"(r3) : "r"(addr));
}
__device__ __forceinline__ void ldsm2(uint32_t& r0, uint32_t& r1, uint32_t addr) {
    asm volatile("ldmatrix.sync.aligned.m8n8.x2.shared.b16 {%0,%1}, [%2];"
        : "=r"(r0), "=r"(r1) : "r"(addr));
}
__device__ __forceinline__ void hmma(float* c, const uint32_t* a, const uint32_t* b) {
    asm volatile(
        "mma.sync.aligned.m16n8k16.row.col.f32.f16.f16.f32 "
        "{%0,%1,%2,%3}, {%4,%5,%6,%7}, {%8,%9}, {%0,%1,%2,%3};"
        : "+f"(c[0]), "+f"(c[1]), "+f"(c[2]), "+f"(c[3])
        : "r"(a[0]), "r"(a[1]), "r"(a[2]), "r"(a[3]), "r"(b[0]), "r"(b[1]));
}
__device__ __forceinline__ void tri_decode(int bid, int& lo, int& hi) {
    int r = (int)((sqrtf(8.0f * (float)bid + 1.0f) - 1.0f) * 0.5f);
    while ((r + 1) * (r + 2) / 2 <= bid) ++r;
    while (r * (r + 1) / 2 > bid) --r;
    hi = r;
    lo = bid - r * (r + 1) / 2;
}

// ---------------- kernels ----------------

__global__ void k_feat(const float* __restrict__ x) {
    int n = blockIdx.x * blockDim.x + threadIdx.x;
    if (n >= NPIX) return;
    int y = n / HH, xc = n % HH;
    float f0 = (float)y  * (1.0f / 30.0f);
    float f1 = (float)xc * (1.0f / 30.0f);
    float f2 = x[n]            * 10.0f;
    float f3 = x[NPIX + n]     * 10.0f;
    float f4 = x[2 * NPIX + n] * 10.0f;
    float sq = f0*f0 + f1*f1 + f2*f2 + f3*f3 + f4*f4;
    g_feat[n]            = sq;
    g_feat[NPIX     + n] = f0;
    g_feat[2*NPIX   + n] = f1;
    g_feat[3*NPIX   + n] = f2;
    g_feat[4*NPIX   + n] = f3;
    g_feat[5*NPIX   + n] = f4;
    if (n < HH) g_gauss[n] = expf(-(float)(n * n) * (1.0f / 18.0f));
}

// Upper-tri build into tile-contiguous swizzled layout (fp16 hi only).
__global__ void __launch_bounds__(256) k_build_t() {
    int ta, tb;
    tri_decode(blockIdx.x, ta, tb);        // ta <= tb
    size_t tbase = (size_t)blockIdx.x * 8192;
    int tid = threadIdx.x;
    int r  = tid >> 2;
    int cq = (tid & 3) * 16;

    int a = ta * 64 + r;
    float sqa = g_feat[a];
    float a0 = g_feat[NPIX   + a];
    float a1 = g_feat[2*NPIX + a];
    float a2 = g_feat[3*NPIX + a];
    float a3 = g_feat[4*NPIX + a];
    float a4 = g_feat[5*NPIX + a];

    char* Kh = (char*)g_Khi + tbase;
    #pragma unroll
    for (int q = 0; q < 8; ++q) {
        int col = cq + 2 * q;
        int b = tb * 64 + col;
        float2 sqb = *(const float2*)&g_feat[b];
        float2 b0  = *(const float2*)&g_feat[NPIX   + b];
        float2 b1  = *(const float2*)&g_feat[2*NPIX + b];
        float2 b2  = *(const float2*)&g_feat[3*NPIX + b];
        float2 b3  = *(const float2*)&g_feat[4*NPIX + b];
        float2 b4  = *(const float2*)&g_feat[5*NPIX + b];
        float dotx = a0*b0.x + a1*b1.x + a2*b2.x + a3*b3.x + a4*b4.x;
        float doty = a0*b0.y + a1*b1.y + a2*b2.y + a3*b3.y + a4*b4.y;
        float kx = APP_W * __expf(-0.5f * fmaxf(sqa + sqb.x - 2.0f * dotx, 0.0f));
        float ky = APP_W * __expf(-0.5f * fmaxf(sqa + sqb.y - 2.0f * doty, 0.0f));
        uint32_t off = SW((uint32_t)(r * 128 + col * 2));
        *(__half2*)(Kh + off) = __halves2half2(__float2half_rn(kx), __float2half_rn(ky));
    }
}

__device__ __forceinline__ void write_probs(int n, const float* u, float inv, float* out_cm) {
    int blk = n >> 6, wi = n & 63;
    char* Bh = (char*)g_Bhi + (size_t)blk * 3072;
    char* Bl = (char*)g_Blo + (size_t)blk * 3072;
    #pragma unroll
    for (int c = 0; c < CC; c++) {
        float o = u[c] * inv;
        out_cm[c * NPIX + n] = o;
        __half h = __float2half_rn(o);
        uint32_t off = SW((uint32_t)(c * 128 + wi * 2));
        *(__half*)(Bh + off) = h;
        *(__half*)(Bl + off) = __float2half_rn(o - __half2float(h));
    }
}

__global__ void k_init(const float* __restrict__ yhat, float* __restrict__ out_cm) {
    int n = blockIdx.x * blockDim.x + threadIdx.x;
    if (n >= NPIX) return;
    float u[CC];
    float mx = -1e30f;
    #pragma unroll
    for (int c = 0; c < CC; c++) {
        float v = yhat[c * NPIX + n];
        g_unary[c * NPIX + n] = v;
        u[c] = v;
        mx = fmaxf(mx, v);
    }
    float s = 0.0f;
    #pragma unroll
    for (int c = 0; c < CC; c++) { u[c] = __expf(u[c] - mx); s += u[c]; }
    write_probs(n, u, 1.0f / s, out_cm);
    int blk = n >> 6, wi = n & 63;
    char* Bh = (char*)g_Bhi + (size_t)blk * 3072;
    char* Bl = (char*)g_Blo + (size_t)blk * 3072;
    #pragma unroll
    for (int c = CC; c < NB; c++) {
        uint32_t off = SW((uint32_t)(c * 128 + wi * 2));
        *(__half*)(Bh + off) = __float2half_rn(0.0f);
        *(__half*)(Bl + off) = __float2half_rn(0.0f);
    }
}

// thread-0 stage fill: 6 bulk copies (2 A-tiles + 4 P-planes)
__device__ __forceinline__ void fill_stage(uint32_t st, int I, int J0, uint32_t mb) {
    #pragma unroll
    for (int k = 0; k < 2; ++k) {
        int J = (k == 0) ? J0 : ((J0 + 1 == NBLK) ? 0 : J0 + 1);
        int lo = (I < J) ? I : J;
        int hi = (I < J) ? J : I;
        size_t tb2 = (size_t)(hi * (hi + 1) / 2 + lo) * 8192;
        bulk_cp(st + A0OF + k * 8192, (char*)g_Khi + tb2, 8192, mb);
        bulk_cp(st + P0HI + k * 6144, (char*)g_Bhi + (size_t)J * 3072, 3072, mb);
        bulk_cp(st + P0LO + k * 6144, (char*)g_Blo + (size_t)J * 3072, 3072, mb);
    }
}

// Owner-computes symmetric GEMM, 2-term (Khi*Phi + Khi*Plo), paired L2 schedule.
__global__ void __launch_bounds__(256, 2) k_gemm_sym4() {
    extern __shared__ char smem[];
    __shared__ uint64_t mbar_s[NSTAGE];
    uint32_t sb = smem_u32(smem);
    int tid = threadIdx.x;
    int lane = tid & 31;
    int w = tid >> 5;
    int r = w & 3;           // 16-row group
    int kh = w >> 2;         // k-half
    int I = blockIdx.x;
    int h = blockIdx.y;
    int Jbase = (72 * h - I + 2 * NBLK) % NBLK;

    uint32_t mb[NSTAGE];
    #pragma unroll
    for (int s = 0; s < NSTAGE; s++) mb[s] = smem_u32(&mbar_s[s]);
    if (tid < NSTAGE) mbar_init(mb[tid], 1);
    __syncthreads();
    if (tid == 0) {
        #pragma unroll
        for (int s = 0; s < NSTAGE; s++) {
            mbar_expect_tx(mb[s], FULLB);
            int J0 = Jbase + 2 * s; if (J0 >= NBLK) J0 -= NBLK;
            fill_stage(sb + s * STAGEB, I, J0, mb[s]);
        }
    }

    // --- precomputed swizzled frag offsets ---
    int arow = r * 16 + (lane & 15);
    int ach = (lane >> 4) + kh * 4;
    uint32_t a_sw[2];
    #pragma unroll
    for (int ks = 0; ks < 2; ks++)
        a_sw[ks] = (uint32_t)(arow * 128 + (((ach + ks * 2) ^ (arow & 7)) << 4));
    int gg = lane >> 3;
    int tch = r * 2 + (gg & 1);
    int trow = kh * 32 + (gg >> 1) * 8 + (lane & 7);
    uint32_t t_sw[2];
    #pragma unroll
    for (int ks = 0; ks < 2; ks++)
        t_sw[ks] = (uint32_t)((trow + ks * 16) * 128 + ((tch ^ (lane & 7)) << 4));
    // B: x4 covers nt0 (lanes 0-15) + nt1 (lanes 16-31); x2 covers nt2
    int l2 = lane & 15;
    int brl = l2 & 7;
    int bch = ((l2 >> 3) & 1) + kh * 4;
    uint32_t b4_sw[2], b2_sw[2];
    #pragma unroll
    for (int ks = 0; ks < 2; ks++) {
        b4_sw[ks] = (uint32_t)((((lane >> 4) * 8) + brl) * 128 + (((bch + ks * 2) ^ brl) << 4));
        b2_sw[ks] = (uint32_t)((16 + brl) * 128 + (((bch + ks * 2) ^ brl) << 4));
    }

    float acc[2][3][4];
    #pragma unroll
    for (int tm = 0; tm < 2; tm++)
        #pragma unroll
        for (int nt = 0; nt < 3; nt++)
            #pragma unroll
            for (int q = 0; q < 4; q++) acc[tm][nt][q] = 0.0f;

    for (int t = 0; t < NSTEP; ++t) {
        int s = t % NSTAGE;
        uint32_t st = sb + s * STAGEB;
        mbar_wait(mb[s], (t / NSTAGE) & 1);

        #pragma unroll
        for (int k = 0; k < 2; ++k) {
            int u = 2 * t + k;
            int J = Jbase + u; if (J >= NBLK) J -= NBLK;
            uint32_t Ah = st + A0OF + k * 8192;
            uint32_t Ph = st + P0HI + k * 6144;
            uint32_t Pl = st + P0LO + k * 6144;
            #pragma unroll
            for (int ks = 0; ks < 2; ++ks) {
                uint32_t ah[4];
                if (J >= I) ldsm4(ah[0], ah[1], ah[2], ah[3], Ah + a_sw[ks]);
                else        ldsm4t(ah[0], ah[1], ah[2], ah[3], Ah + t_sw[ks]);
                uint32_t bh[4], bh2[2], bl[4], bl2[2];
                ldsm4(bh[0], bh[1], bh[2], bh[3], Ph + b4_sw[ks]);
                ldsm2(bh2[0], bh2[1], Ph + b2_sw[ks]);
                ldsm4(bl[0], bl[1], bl[2], bl[3], Pl + b4_sw[ks]);
                ldsm2(bl2[0], bl2[1], Pl + b2_sw[ks]);
                hmma(acc[0][0], ah, bh);
                hmma(acc[0][1], ah, bh + 2);
                hmma(acc[0][2], ah, bh2);
                hmma(acc[1][0], ah, bl);
                hmma(acc[1][1], ah, bl + 2);
                hmma(acc[1][2], ah, bl2);
            }
        }
        __syncthreads();
        if (t + NSTAGE < NSTEP && tid == 0) {
            mbar_expect_tx(mb[s], FULLB);
            int J0 = Jbase + 2 * (t + NSTAGE); if (J0 >= NBLK) J0 -= NBLK;
            fill_stage(st, I, J0, mb[s]);
        }
    }

    // epilogue: 2-term sum, k-half reduction via smem, single STG
    float sum_[3][4];
    #pragma unroll
    for (int nt = 0; nt < 3; nt++)
        #pragma unroll
        for (int q = 0; q < 4; q++)
            sum_[nt][q] = acc[0][nt][q] + acc[1][nt][q];

    float* red = (float*)smem;
    int row16 = lane >> 2;
    int cb = (lane & 3) * 2;
    if (kh == 1) {
        #pragma unroll
        for (int nt = 0; nt < 3; ++nt) {
            red[(r * 16 + row16) * 26 + nt * 8 + cb]         = sum_[nt][0];
            red[(r * 16 + row16) * 26 + nt * 8 + cb + 1]     = sum_[nt][1];
            red[(r * 16 + row16 + 8) * 26 + nt * 8 + cb]     = sum_[nt][2];
            red[(r * 16 + row16 + 8) * 26 + nt * 8 + cb + 1] = sum_[nt][3];
        }
    }
    __syncthreads();
    if (kh == 0) {
        float* dst = g_part[h];
        int rg0 = I * 64 + r * 16 + row16;
        #pragma unroll
        for (int nt = 0; nt < 3; ++nt) {
            float s0 = sum_[nt][0] + red[(r * 16 + row16) * 26 + nt * 8 + cb];
            float s1 = sum_[nt][1] + red[(r * 16 + row16) * 26 + nt * 8 + cb + 1];
            float s2 = sum_[nt][2] + red[(r * 16 + row16 + 8) * 26 + nt * 8 + cb];
            float s3 = sum_[nt][3] + red[(r * 16 + row16 + 8) * 26 + nt * 8 + cb + 1];
            *(float2*)&dst[(size_t)rg0 * NB + nt * 8 + cb]       = make_float2(s0, s1);
            *(float2*)&dst[(size_t)(rg0 + 8) * NB + nt * 8 + cb] = make_float2(s2, s3);
        }
    }
}

// Fused separable smoothness (row + col conv) per channel, all in smem.
__global__ void __launch_bounds__(512) k_conv(const float* __restrict__ out_cm) {
    extern __shared__ float cbuf[];
    float* img = cbuf;            // 9216
    float* tmp = cbuf + NPIX;     // 9216
    float* sg  = cbuf + 2 * NPIX; // 96
    int c = blockIdx.x;
    int tid = threadIdx.x;
    if (tid < HH) sg[tid] = g_gauss[tid];
    for (int i = tid; i < NPIX; i += 512) img[i] = out_cm[c * NPIX + i];
    __syncthreads();
    // row pass
    for (int i = tid; i < NPIX; i += 512) {
        int xp = i % HH;
        const float* row = img + (i - xp);
        float s = 0.0f;
        #pragma unroll 8
        for (int xx = 0; xx < HH; ++xx) {
            int d = xx - xp; d = (d < 0) ? -d : d;
            s += row[xx] * sg[d];
        }
        tmp[i] = s;
    }
    __syncthreads();
    // col pass
    for (int i = tid; i < NPIX; i += 512) {
        int xp = i % HH;
        int yp = i / HH;
        const float* col = tmp + xp;
        float s = 0.0f;
        #pragma unroll 8
        for (int y = 0; y < HH; ++y) {
            int d = y - yp; d = (d < 0) ? -d : d;
            s += col[y * HH] * sg[d];
        }
        g_smo[c * NPIX + i] = s;
    }
}

__global__ void k_combine(const float* __restrict__ mu, float* __restrict__ out_cm) {
    __shared__ float smu[CC * CC];
    for (int i = threadIdx.x; i < CC * CC; i += blockDim.x) smu[i] = mu[i];
    __syncthreads();
    int n = blockIdx.x * blockDim.x + threadIdx.x;
    if (n >= NPIX) return;
    float m[CC];
    #pragma unroll
    for (int c = 0; c < CC; c++)
        m[c] = g_part[0][(size_t)n * NB + c] + g_part[1][(size_t)n * NB + c]
             + SMO_W * g_smo[c * NPIX + n];
    float u[CC];
    float mx = -1e30f;
    #pragma unroll
    for (int c = 0; c < CC; c++) {
        float s = 0.0f;
        #pragma unroll
        for (int c2 = 0; c2 < CC; c2++) s = fmaf(smu[c2 * CC + c], m[c2], s);
        float v = g_unary[c * NPIX + n] + s;
        g_unary[c * NPIX + n] = v;
        u[c] = v;
        mx = fmaxf(mx, v);
    }
    float s = 0.0f;
    #pragma unroll
    for (int c = 0; c < CC; c++) { u[c] = __expf(u[c] - mx); s += u[c]; }
    write_probs(n, u, 1.0f / s, out_cm);
}

// ---------------- launch ----------------
extern "C" void kernel_launch(void* const* d_in, const int* in_sizes, int n_in,
                              void* d_out, int out_size) {
    const float* x    = (const float*)d_in[0];
    const float* yhat = (const float*)d_in[1];
    const float* mu   = (const float*)d_in[2];
    float* out = (float*)d_out;

    const int conv_smem = (2 * NPIX + HH) * sizeof(float);
    cudaFuncSetAttribute(k_gemm_sym4, cudaFuncAttributeMaxDynamicSharedMemorySize, GEMM_SMEM);
    cudaFuncSetAttribute(k_conv, cudaFuncAttributeMaxDynamicSharedMemorySize, conv_smem);

    k_feat<<<(NPIX + 255) / 256, 256>>>(x);
    k_build_t<<<NTILE, 256>>>();
    k_init<<<(NPIX + 255) / 256, 256>>>(yhat, out);

    for (int it = 0; it < CRF_ITERS; ++it) {
        k_gemm_sym4<<<dim3(NBLK, 2), 256, GEMM_SMEM>>>();
        k_conv<<<CC, 512, conv_smem>>>(out);
        k_combine<<<(NPIX + 127) / 128, 128>>>(mu, out);
    }
}

// round 9
// speedup vs baseline: 1.7126x; 1.7126x over previous
#include <cuda_runtime.h>
#include <cuda_fp16.h>
#include <cstdint>

#define NPIX 9216
#define HH 96
#define CC 21
#define NB 24
#define CRF_ITERS 5
#define APP_W 10.0f
#define SMO_W 3.0f

#define NBLK 144                        // 64-pixel blocks
#define NTILE (NBLK * (NBLK + 1) / 2)   // 10440 stored upper-tri tiles
#define NSPLIT 3                        // split-K over J-blocks
#define NSTEP 24                        // 48 J-blocks per CTA, 2 per step

// smem stage layout (bytes): 2 A-tiles (hi only) + 2 P-tiles (hi+lo)
#define A0OF 0
#define A1OF 8192
#define P0HI 16384
#define P0LO 19456
#define P1HI 22528
#define P1LO 25600
#define STAGEB 28672
#define NSTAGE 2
#define GEMM_SMEM (NSTAGE * STAGEB)     // 57344
#define FULLB 28672

// XOR swizzle baked into gmem tile layout
#define SW(off) ((off) ^ ((((off) >> 7) & 7) << 4))

// ---------------- persistent device scratch ----------------
static __device__ __half g_Khi[(size_t)NTILE * 4096];  // 85.5 MB, tile-contiguous
static __device__ float  g_feat[6 * NPIX];
static __device__ float  g_gauss[HH];
static __device__ float  g_unary[CC * NPIX];
static __device__ __half g_Bhi[NBLK * NB * 64];        // [block][class][64], swizzled
static __device__ __half g_Blo[NBLK * NB * 64];
static __device__ float  g_part[NSPLIT][(size_t)NPIX * NB];
static __device__ float  g_tmp[CC * NPIX];
static __device__ float  g_smo[CC * NPIX];

// ---------------- PTX helpers ----------------
__device__ __forceinline__ uint32_t smem_u32(const void* p) {
    uint32_t a;
    asm("{ .reg .u64 t; cvta.to.shared.u64 t, %1; cvt.u32.u64 %0, t; }" : "=r"(a) : "l"(p));
    return a;
}
__device__ __forceinline__ void mbar_init(uint32_t a, uint32_t c) {
    asm volatile("mbarrier.init.shared.b64 [%0], %1;" :: "r"(a), "r"(c) : "memory");
}
__device__ __forceinline__ void mbar_expect_tx(uint32_t a, uint32_t bytes) {
    asm volatile("mbarrier.arrive.expect_tx.shared.b64 _, [%0], %1;" :: "r"(a), "r"(bytes) : "memory");
}
__device__ __forceinline__ void mbar_wait(uint32_t mbar, uint32_t parity) {
    asm volatile(
        "{\n\t.reg .pred P1;\n\t"
        "WL%=:\n\t"
        "mbarrier.try_wait.parity.shared.b64 P1, [%0], %1;\n\t"
        "@!P1 bra WL%=;\n\t}"
        :: "r"(mbar), "r"(parity) : "memory");
}
__device__ __forceinline__ void bulk_cp(uint32_t dst, const void* src, uint32_t bytes, uint32_t mbar) {
    asm volatile(
        "cp.async.bulk.shared::cluster.global.mbarrier::complete_tx::bytes [%0], [%1], %2, [%3];"
        :: "r"(dst), "l"(src), "r"(bytes), "r"(mbar) : "memory");
}
__device__ __forceinline__ void ldsm4(uint32_t& r0, uint32_t& r1, uint32_t& r2, uint32_t& r3, uint32_t addr) {
    asm volatile("ldmatrix.sync.aligned.m8n8.x4.shared.b16 {%0,%1,%2,%3}, [%4];"
        : "=r"(r0), "=r"(r1), "=r"(r2), "=r"(r3) : "r"(addr));
}
__device__ __forceinline__ void ldsm4t(uint32_t& r0, uint32_t& r1, uint32_t& r2, uint32_t& r3, uint32_t addr) {
    asm volatile("ldmatrix.sync.aligned.m8n8.x4.trans.shared.b16 {%0,%1,%2,%3}, [%4];"
        : "=r"(r0), "=r"(r1), "=r"(r2), "=r"(r3) : "r"(addr));
}
__device__ __forceinline__ void ldsm2(uint32_t& r0, uint32_t& r1, uint32_t addr) {
    asm volatile("ldmatrix.sync.aligned.m8n8.x2.shared.b16 {%0,%1}, [%2];"
        : "=r"(r0), "=r"(r1) : "r"(addr));
}
__device__ __forceinline__ void hmma(float* c, const uint32_t* a, const uint32_t* b) {
    asm volatile(
        "mma.sync.aligned.m16n8k16.row.col.f32.f16.f16.f32 "
        "{%0,%1,%2,%3}, {%4,%5,%6,%7}, {%8,%9}, {%0,%1,%2,%3};"
        : "+f"(c[0]), "+f"(c[1]), "+f"(c[2]), "+f"(c[3])
        : "r"(a[0]), "r"(a[1]), "r"(a[2]), "r"(a[3]), "r"(b[0]), "r"(b[1]));
}
__device__ __forceinline__ void tri_decode(int bid, int& lo, int& hi) {
    int r = (int)((sqrtf(8.0f * (float)bid + 1.0f) - 1.0f) * 0.5f);
    while ((r + 1) * (r + 2) / 2 <= bid) ++r;
    while (r * (r + 1) / 2 > bid) --r;
    hi = r;
    lo = bid - r * (r + 1) / 2;
}

// ---------------- kernels ----------------

__global__ void k_feat(const float* __restrict__ x) {
    int n = blockIdx.x * blockDim.x + threadIdx.x;
    if (n >= NPIX) return;
    int y = n / HH, xc = n % HH;
    float f0 = (float)y  * (1.0f / 30.0f);
    float f1 = (float)xc * (1.0f / 30.0f);
    float f2 = x[n]            * 10.0f;
    float f3 = x[NPIX + n]     * 10.0f;
    float f4 = x[2 * NPIX + n] * 10.0f;
    float sq = f0*f0 + f1*f1 + f2*f2 + f3*f3 + f4*f4;
    g_feat[n]            = sq;
    g_feat[NPIX     + n] = f0;
    g_feat[2*NPIX   + n] = f1;
    g_feat[3*NPIX   + n] = f2;
    g_feat[4*NPIX   + n] = f3;
    g_feat[5*NPIX   + n] = f4;
    if (n < HH) g_gauss[n] = expf(-(float)(n * n) * (1.0f / 18.0f));
}

// Upper-tri build into tile-contiguous swizzled layout (fp16 hi only).
__global__ void __launch_bounds__(256) k_build_t() {
    int ta, tb;
    tri_decode(blockIdx.x, ta, tb);        // ta <= tb
    size_t tbase = (size_t)blockIdx.x * 8192;
    int tid = threadIdx.x;
    int r  = tid >> 2;
    int cq = (tid & 3) * 16;

    int a = ta * 64 + r;
    float sqa = g_feat[a];
    float a0 = g_feat[NPIX   + a];
    float a1 = g_feat[2*NPIX + a];
    float a2 = g_feat[3*NPIX + a];
    float a3 = g_feat[4*NPIX + a];
    float a4 = g_feat[5*NPIX + a];

    char* Kh = (char*)g_Khi + tbase;
    #pragma unroll
    for (int q = 0; q < 8; ++q) {
        int col = cq + 2 * q;
        int b = tb * 64 + col;
        float2 sqb = *(const float2*)&g_feat[b];
        float2 b0  = *(const float2*)&g_feat[NPIX   + b];
        float2 b1  = *(const float2*)&g_feat[2*NPIX + b];
        float2 b2  = *(const float2*)&g_feat[3*NPIX + b];
        float2 b3  = *(const float2*)&g_feat[4*NPIX + b];
        float2 b4  = *(const float2*)&g_feat[5*NPIX + b];
        float dotx = a0*b0.x + a1*b1.x + a2*b2.x + a3*b3.x + a4*b4.x;
        float doty = a0*b0.y + a1*b1.y + a2*b2.y + a3*b3.y + a4*b4.y;
        float kx = APP_W * __expf(-0.5f * fmaxf(sqa + sqb.x - 2.0f * dotx, 0.0f));
        float ky = APP_W * __expf(-0.5f * fmaxf(sqa + sqb.y - 2.0f * doty, 0.0f));
        uint32_t off = SW((uint32_t)(r * 128 + col * 2));
        *(__half2*)(Kh + off) = __halves2half2(__float2half_rn(kx), __float2half_rn(ky));
    }
}

__device__ __forceinline__ void write_probs(int n, const float* u, float inv, float* out_cm) {
    int blk = n >> 6, wi = n & 63;
    char* Bh = (char*)g_Bhi + (size_t)blk * 3072;
    char* Bl = (char*)g_Blo + (size_t)blk * 3072;
    #pragma unroll
    for (int c = 0; c < CC; c++) {
        float o = u[c] * inv;
        out_cm[c * NPIX + n] = o;
        __half h = __float2half_rn(o);
        uint32_t off = SW((uint32_t)(c * 128 + wi * 2));
        *(__half*)(Bh + off) = h;
        *(__half*)(Bl + off) = __float2half_rn(o - __half2float(h));
    }
}

__global__ void k_init(const float* __restrict__ yhat, float* __restrict__ out_cm) {
    int n = blockIdx.x * blockDim.x + threadIdx.x;
    if (n >= NPIX) return;
    float u[CC];
    float mx = -1e30f;
    #pragma unroll
    for (int c = 0; c < CC; c++) {
        float v = yhat[c * NPIX + n];
        g_unary[c * NPIX + n] = v;
        u[c] = v;
        mx = fmaxf(mx, v);
    }
    float s = 0.0f;
    #pragma unroll
    for (int c = 0; c < CC; c++) { u[c] = __expf(u[c] - mx); s += u[c]; }
    write_probs(n, u, 1.0f / s, out_cm);
    int blk = n >> 6, wi = n & 63;
    char* Bh = (char*)g_Bhi + (size_t)blk * 3072;
    char* Bl = (char*)g_Blo + (size_t)blk * 3072;
    #pragma unroll
    for (int c = CC; c < NB; c++) {
        uint32_t off = SW((uint32_t)(c * 128 + wi * 2));
        *(__half*)(Bh + off) = __float2half_rn(0.0f);
        *(__half*)(Bl + off) = __float2half_rn(0.0f);
    }
}

// thread-0 stage fill: 6 bulk copies (2 A-tiles + 4 P-planes)
__device__ __forceinline__ void fill_stage(uint32_t st, int I, int J0, uint32_t mb) {
    #pragma unroll
    for (int k = 0; k < 2; ++k) {
        int J = (k == 0) ? J0 : ((J0 + 1 == NBLK) ? 0 : J0 + 1);
        int lo = (I < J) ? I : J;
        int hi = (I < J) ? J : I;
        size_t tb2 = (size_t)(hi * (hi + 1) / 2 + lo) * 8192;
        bulk_cp(st + A0OF + k * 8192, (char*)g_Khi + tb2, 8192, mb);
        bulk_cp(st + P0HI + k * 6144, (char*)g_Bhi + (size_t)J * 3072, 3072, mb);
        bulk_cp(st + P0LO + k * 6144, (char*)g_Blo + (size_t)J * 3072, 3072, mb);
    }
}

// Owner-computes symmetric GEMM, 2-term (Khi*Phi + Khi*Plo), paired L2 schedule,
// 3-way split-K over J, 3 CTAs/SM.
__global__ void __launch_bounds__(256, 3) k_gemm_sym5() {
    extern __shared__ char smem[];
    __shared__ uint64_t mbar_s[NSTAGE];
    uint32_t sb = smem_u32(smem);
    int tid = threadIdx.x;
    int lane = tid & 31;
    int w = tid >> 5;
    int r = w & 3;           // 16-row group
    int kh = w >> 2;         // k-half
    int I = blockIdx.x;
    int h = blockIdx.y;
    int Jbase = (48 * h - I + 2 * NBLK) % NBLK;

    uint32_t mb[NSTAGE];
    #pragma unroll
    for (int s = 0; s < NSTAGE; s++) mb[s] = smem_u32(&mbar_s[s]);
    if (tid < NSTAGE) mbar_init(mb[tid], 1);
    __syncthreads();
    if (tid == 0) {
        #pragma unroll
        for (int s = 0; s < NSTAGE; s++) {
            mbar_expect_tx(mb[s], FULLB);
            int J0 = Jbase + 2 * s; if (J0 >= NBLK) J0 -= NBLK;
            fill_stage(sb + s * STAGEB, I, J0, mb[s]);
        }
    }

    // --- precomputed swizzled frag offsets ---
    int arow = r * 16 + (lane & 15);
    int ach = (lane >> 4) + kh * 4;
    uint32_t a_sw[2];
    #pragma unroll
    for (int ks = 0; ks < 2; ks++)
        a_sw[ks] = (uint32_t)(arow * 128 + (((ach + ks * 2) ^ (arow & 7)) << 4));
    int gg = lane >> 3;
    int tch = r * 2 + (gg & 1);
    int trow = kh * 32 + (gg >> 1) * 8 + (lane & 7);
    uint32_t t_sw[2];
    #pragma unroll
    for (int ks = 0; ks < 2; ks++)
        t_sw[ks] = (uint32_t)((trow + ks * 16) * 128 + ((tch ^ (lane & 7)) << 4));
    // B: x4 covers nt0 (lanes 0-15) + nt1 (lanes 16-31); x2 covers nt2
    int l2 = lane & 15;
    int brl = l2 & 7;
    int bch = ((l2 >> 3) & 1) + kh * 4;
    uint32_t b4_sw[2], b2_sw[2];
    #pragma unroll
    for (int ks = 0; ks < 2; ks++) {
        b4_sw[ks] = (uint32_t)((((lane >> 4) * 8) + brl) * 128 + (((bch + ks * 2) ^ brl) << 4));
        b2_sw[ks] = (uint32_t)((16 + brl) * 128 + (((bch + ks * 2) ^ brl) << 4));
    }

    float acc[2][3][4];
    #pragma unroll
    for (int tm = 0; tm < 2; tm++)
        #pragma unroll
        for (int nt = 0; nt < 3; nt++)
            #pragma unroll
            for (int q = 0; q < 4; q++) acc[tm][nt][q] = 0.0f;

    for (int t = 0; t < NSTEP; ++t) {
        int s = t & 1;
        uint32_t st = sb + s * STAGEB;
        mbar_wait(mb[s], (t >> 1) & 1);

        #pragma unroll
        for (int k = 0; k < 2; ++k) {
            int u = 2 * t + k;
            int J = Jbase + u; if (J >= NBLK) J -= NBLK;
            uint32_t Ah = st + A0OF + k * 8192;
            uint32_t Ph = st + P0HI + k * 6144;
            uint32_t Pl = st + P0LO + k * 6144;
            #pragma unroll
            for (int ks = 0; ks < 2; ++ks) {
                uint32_t ah[4];
                if (J >= I) ldsm4(ah[0], ah[1], ah[2], ah[3], Ah + a_sw[ks]);
                else        ldsm4t(ah[0], ah[1], ah[2], ah[3], Ah + t_sw[ks]);
                uint32_t bh[4], bh2[2], bl[4], bl2[2];
                ldsm4(bh[0], bh[1], bh[2], bh[3], Ph + b4_sw[ks]);
                ldsm2(bh2[0], bh2[1], Ph + b2_sw[ks]);
                ldsm4(bl[0], bl[1], bl[2], bl[3], Pl + b4_sw[ks]);
                ldsm2(bl2[0], bl2[1], Pl + b2_sw[ks]);
                hmma(acc[0][0], ah, bh);
                hmma(acc[0][1], ah, bh + 2);
                hmma(acc[0][2], ah, bh2);
                hmma(acc[1][0], ah, bl);
                hmma(acc[1][1], ah, bl + 2);
                hmma(acc[1][2], ah, bl2);
            }
        }
        __syncthreads();
        if (t + NSTAGE < NSTEP && tid == 0) {
            mbar_expect_tx(mb[s], FULLB);
            int J0 = Jbase + 2 * (t + NSTAGE); if (J0 >= NBLK) J0 -= NBLK;
            fill_stage(st, I, J0, mb[s]);
        }
    }

    // epilogue: 2-term sum, k-half reduction via smem, single STG
    float sum_[3][4];
    #pragma unroll
    for (int nt = 0; nt < 3; nt++)
        #pragma unroll
        for (int q = 0; q < 4; q++)
            sum_[nt][q] = acc[0][nt][q] + acc[1][nt][q];

    float* red = (float*)smem;   // aliases stage 0 (last compute uses stage 1)
    int row16 = lane >> 2;
    int cb = (lane & 3) * 2;
    if (kh == 1) {
        #pragma unroll
        for (int nt = 0; nt < 3; ++nt) {
            red[(r * 16 + row16) * 26 + nt * 8 + cb]         = sum_[nt][0];
            red[(r * 16 + row16) * 26 + nt * 8 + cb + 1]     = sum_[nt][1];
            red[(r * 16 + row16 + 8) * 26 + nt * 8 + cb]     = sum_[nt][2];
            red[(r * 16 + row16 + 8) * 26 + nt * 8 + cb + 1] = sum_[nt][3];
        }
    }
    __syncthreads();
    if (kh == 0) {
        float* dst = g_part[h];
        int rg0 = I * 64 + r * 16 + row16;
        #pragma unroll
        for (int nt = 0; nt < 3; ++nt) {
            float s0 = sum_[nt][0] + red[(r * 16 + row16) * 26 + nt * 8 + cb];
            float s1 = sum_[nt][1] + red[(r * 16 + row16) * 26 + nt * 8 + cb + 1];
            float s2 = sum_[nt][2] + red[(r * 16 + row16 + 8) * 26 + nt * 8 + cb];
            float s3 = sum_[nt][3] + red[(r * 16 + row16 + 8) * 26 + nt * 8 + cb + 1];
            *(float2*)&dst[(size_t)rg0 * NB + nt * 8 + cb]       = make_float2(s0, s1);
            *(float2*)&dst[(size_t)(rg0 + 8) * NB + nt * 8 + cb] = make_float2(s2, s3);
        }
    }
}

// Separable smoothness: horizontal pass (wide grid).
__global__ void k_convx(const float* __restrict__ out_cm) {
    __shared__ float sg[HH];
    if (threadIdx.x < HH) sg[threadIdx.x] = g_gauss[threadIdx.x];
    __syncthreads();
    int idx = blockIdx.x * blockDim.x + threadIdx.x;
    if (idx >= CC * NPIX) return;
    int xp = idx % HH;
    const float* row = out_cm + (idx - xp);
    float s = 0.0f;
    #pragma unroll 8
    for (int xx = 0; xx < HH; ++xx) {
        int d = xx - xp; d = (d < 0) ? -d : d;
        s += row[xx] * sg[d];
    }
    g_tmp[idx] = s;
}

// Separable smoothness: vertical pass (wide grid).
__global__ void k_convy() {
    __shared__ float sg[HH];
    if (threadIdx.x < HH) sg[threadIdx.x] = g_gauss[threadIdx.x];
    __syncthreads();
    int idx = blockIdx.x * blockDim.x + threadIdx.x;
    if (idx >= CC * NPIX) return;
    int xp = idx % HH;
    int yp = (idx / HH) % HH;
    int c  = idx / NPIX;
    const float* col = g_tmp + c * NPIX + xp;
    float s = 0.0f;
    #pragma unroll 8
    for (int y = 0; y < HH; ++y) {
        int d = y - yp; d = (d < 0) ? -d : d;
        s += col[y * HH] * sg[d];
    }
    g_smo[idx] = s;
}

__global__ void k_combine(const float* __restrict__ mu, float* __restrict__ out_cm) {
    __shared__ float smu[CC * CC];
    for (int i = threadIdx.x; i < CC * CC; i += blockDim.x) smu[i] = mu[i];
    __syncthreads();
    int n = blockIdx.x * blockDim.x + threadIdx.x;
    if (n >= NPIX) return;
    float m[CC];
    #pragma unroll
    for (int c = 0; c < CC; c++)
        m[c] = g_part[0][(size_t)n * NB + c] + g_part[1][(size_t)n * NB + c]
             + g_part[2][(size_t)n * NB + c] + SMO_W * g_smo[c * NPIX + n];
    float u[CC];
    float mx = -1e30f;
    #pragma unroll
    for (int c = 0; c < CC; c++) {
        float s = 0.0f;
        #pragma unroll
        for (int c2 = 0; c2 < CC; c2++) s = fmaf(smu[c2 * CC + c], m[c2], s);
        float v = g_unary[c * NPIX + n] + s;
        g_unary[c * NPIX + n] = v;
        u[c] = v;
        mx = fmaxf(mx, v);
    }
    float s = 0.0f;
    #pragma unroll
    for (int c = 0; c < CC; c++) { u[c] = __expf(u[c] - mx); s += u[c]; }
    write_probs(n, u, 1.0f / s, out_cm);
}

// ---------------- launch ----------------
extern "C" void kernel_launch(void* const* d_in, const int* in_sizes, int n_in,
                              void* d_out, int out_size) {
    const float* x    = (const float*)d_in[0];
    const float* yhat = (const float*)d_in[1];
    const float* mu   = (const float*)d_in[2];
    float* out = (float*)d_out;

    cudaFuncSetAttribute(k_gemm_sym5, cudaFuncAttributeMaxDynamicSharedMemorySize, GEMM_SMEM);

    k_feat<<<(NPIX + 255) / 256, 256>>>(x);
    k_build_t<<<NTILE, 256>>>();
    k_init<<<(NPIX + 255) / 256, 256>>>(yhat, out);

    for (int it = 0; it < CRF_ITERS; ++it) {
        k_gemm_sym5<<<dim3(NBLK, NSPLIT), 256, GEMM_SMEM>>>();
        k_convx<<<(CC * NPIX + 127) / 128, 128>>>(out);
        k_convy<<<(CC * NPIX + 127) / 128, 128>>>();
        k_combine<<<(NPIX + 127) / 128, 128>>>(mu, out);
    }
}

// round 10
// speedup vs baseline: 2.1967x; 1.2826x over previous
#include <cuda_runtime.h>
#include <cuda_fp16.h>
#include <cstdint>

#define NPIX 9216
#define HH 96
#define CC 21
#define NB 24
#define CRF_ITERS 5
#define APP_W 10.0f
#define SMO_W 3.0f

#define NBLK 144                        // 64-pixel blocks
#define NTILE (NBLK * (NBLK + 1) / 2)   // 10440 stored upper-tri tiles
#define NSPLIT 3                        // split-K over J-blocks
#define NSTEP 24                        // 48 J-blocks per CTA, 2 per step

// smem stage layout (bytes): 2 A-tiles (hi only) + 2 P-tiles (hi+lo)
#define A0OF 0
#define A1OF 8192
#define P0HI 16384
#define P0LO 19456
#define P1HI 22528
#define P1LO 25600
#define STAGEB 28672
#define NSTAGE 2
#define GEMM_SMEM (NSTAGE * STAGEB)     // 57344
#define FULLB 28672

// XOR swizzle baked into gmem tile layout
#define SW(off) ((off) ^ ((((off) >> 7) & 7) << 4))

// ---------------- persistent device scratch ----------------
static __device__ __half g_Khi[(size_t)NTILE * 4096];  // 85.5 MB, tile-contiguous
static __device__ float  g_feat[6 * NPIX];
static __device__ float  g_gauss[HH];
static __device__ float  g_unary[CC * NPIX];
static __device__ __half g_Bhi[NBLK * NB * 64];        // [block][class][64], swizzled
static __device__ __half g_Blo[NBLK * NB * 64];
static __device__ float  g_part[NSPLIT][(size_t)NPIX * NB];

// ---------------- PTX helpers ----------------
__device__ __forceinline__ uint32_t smem_u32(const void* p) {
    uint32_t a;
    asm("{ .reg .u64 t; cvta.to.shared.u64 t, %1; cvt.u32.u64 %0, t; }" : "=r"(a) : "l"(p));
    return a;
}
__device__ __forceinline__ void mbar_init(uint32_t a, uint32_t c) {
    asm volatile("mbarrier.init.shared.b64 [%0], %1;" :: "r"(a), "r"(c) : "memory");
}
__device__ __forceinline__ void mbar_expect_tx(uint32_t a, uint32_t bytes) {
    asm volatile("mbarrier.arrive.expect_tx.shared.b64 _, [%0], %1;" :: "r"(a), "r"(bytes) : "memory");
}
__device__ __forceinline__ void mbar_wait(uint32_t mbar, uint32_t parity) {
    asm volatile(
        "{\n\t.reg .pred P1;\n\t"
        "WL%=:\n\t"
        "mbarrier.try_wait.parity.shared.b64 P1, [%0], %1;\n\t"
        "@!P1 bra WL%=;\n\t}"
        :: "r"(mbar), "r"(parity) : "memory");
}
__device__ __forceinline__ void bulk_cp(uint32_t dst, const void* src, uint32_t bytes, uint32_t mbar) {
    asm volatile(
        "cp.async.bulk.shared::cluster.global.mbarrier::complete_tx::bytes [%0], [%1], %2, [%3];"
        :: "r"(dst), "l"(src), "r"(bytes), "r"(mbar) : "memory");
}
__device__ __forceinline__ void ldsm4(uint32_t& r0, uint32_t& r1, uint32_t& r2, uint32_t& r3, uint32_t addr) {
    asm volatile("ldmatrix.sync.aligned.m8n8.x4.shared.b16 {%0,%1,%2,%3}, [%4];"
        : "=r"(r0), "=r"(r1), "=r"(r2), "=r"(r3) : "r"(addr));
}
__device__ __forceinline__ void ldsm4t(uint32_t& r0, uint32_t& r1, uint32_t& r2, uint32_t& r3, uint32_t addr) {
    asm volatile("ldmatrix.sync.aligned.m8n8.x4.trans.shared.b16 {%0,%1,%2,%3}, [%4];"
        : "=r"(r0), "=r"(r1), "=r"(r2), "=r"(r3) : "r"(addr));
}
__device__ __forceinline__ void ldsm2(uint32_t& r0, uint32_t& r1, uint32_t addr) {
    asm volatile("ldmatrix.sync.aligned.m8n8.x2.shared.b16 {%0,%1}, [%2];"
        : "=r"(r0), "=r"(r1) : "r"(addr));
}
__device__ __forceinline__ void hmma(float* c, const uint32_t* a, const uint32_t* b) {
    asm volatile(
        "mma.sync.aligned.m16n8k16.row.col.f32.f16.f16.f32 "
        "{%0,%1,%2,%3}, {%4,%5,%6,%7}, {%8,%9}, {%0,%1,%2,%3};"
        : "+f"(c[0]), "+f"(c[1]), "+f"(c[2]), "+f"(c[3])
        : "r"(a[0]), "r"(a[1]), "r"(a[2]), "r"(a[3]), "r"(b[0]), "r"(b[1]));
}
__device__ __forceinline__ void tri_decode(int bid, int& lo, int& hi) {
    int r = (int)((sqrtf(8.0f * (float)bid + 1.0f) - 1.0f) * 0.5f);
    while ((r + 1) * (r + 2) / 2 <= bid) ++r;
    while (r * (r + 1) / 2 > bid) --r;
    hi = r;
    lo = bid - r * (r + 1) / 2;
}

// ---------------- kernels ----------------

__global__ void k_feat(const float* __restrict__ x) {
    int n = blockIdx.x * blockDim.x + threadIdx.x;
    if (n >= NPIX) return;
    int y = n / HH, xc = n % HH;
    float f0 = (float)y  * (1.0f / 30.0f);
    float f1 = (float)xc * (1.0f / 30.0f);
    float f2 = x[n]            * 10.0f;
    float f3 = x[NPIX + n]     * 10.0f;
    float f4 = x[2 * NPIX + n] * 10.0f;
    float sq = f0*f0 + f1*f1 + f2*f2 + f3*f3 + f4*f4;
    g_feat[n]            = sq;
    g_feat[NPIX     + n] = f0;
    g_feat[2*NPIX   + n] = f1;
    g_feat[3*NPIX   + n] = f2;
    g_feat[4*NPIX   + n] = f3;
    g_feat[5*NPIX   + n] = f4;
    if (n < HH) g_gauss[n] = expf(-(float)(n * n) * (1.0f / 18.0f));
}

// Upper-tri build of K_total = APP_W*K_bi + SMO_W*K_sm into tile-contiguous
// swizzled fp16 layout. K_sm(a,b) = g_gauss[|dy|]*g_gauss[|dx|] (separable table).
__global__ void __launch_bounds__(256) k_build_t() {
    __shared__ float sg[HH];
    int ta, tb;
    tri_decode(blockIdx.x, ta, tb);        // ta <= tb
    size_t tbase = (size_t)blockIdx.x * 8192;
    int tid = threadIdx.x;
    if (tid < HH) sg[tid] = g_gauss[tid];
    __syncthreads();
    int r  = tid >> 2;
    int cq = (tid & 3) * 16;

    int a = ta * 64 + r;
    int ya = a / HH, xa = a % HH;
    float sqa = g_feat[a];
    float a0 = g_feat[NPIX   + a];
    float a1 = g_feat[2*NPIX + a];
    float a2 = g_feat[3*NPIX + a];
    float a3 = g_feat[4*NPIX + a];
    float a4 = g_feat[5*NPIX + a];

    char* Kh = (char*)g_Khi + tbase;
    #pragma unroll
    for (int q = 0; q < 8; ++q) {
        int col = cq + 2 * q;
        int b = tb * 64 + col;
        float2 sqb = *(const float2*)&g_feat[b];
        float2 b0  = *(const float2*)&g_feat[NPIX   + b];
        float2 b1  = *(const float2*)&g_feat[2*NPIX + b];
        float2 b2  = *(const float2*)&g_feat[3*NPIX + b];
        float2 b3  = *(const float2*)&g_feat[4*NPIX + b];
        float2 b4  = *(const float2*)&g_feat[5*NPIX + b];
        float dotx = a0*b0.x + a1*b1.x + a2*b2.x + a3*b3.x + a4*b4.x;
        float doty = a0*b0.y + a1*b1.y + a2*b2.y + a3*b3.y + a4*b4.y;
        int yb0 = b / HH, xb0 = b % HH;
        int yb1 = (b + 1) / HH, xb1 = (b + 1) % HH;
        int dy0 = ya - yb0; dy0 = (dy0 < 0) ? -dy0 : dy0;
        int dx0 = xa - xb0; dx0 = (dx0 < 0) ? -dx0 : dx0;
        int dy1 = ya - yb1; dy1 = (dy1 < 0) ? -dy1 : dy1;
        int dx1 = xa - xb1; dx1 = (dx1 < 0) ? -dx1 : dx1;
        float kx = APP_W * __expf(-0.5f * fmaxf(sqa + sqb.x - 2.0f * dotx, 0.0f))
                 + SMO_W * sg[dy0] * sg[dx0];
        float ky = APP_W * __expf(-0.5f * fmaxf(sqa + sqb.y - 2.0f * doty, 0.0f))
                 + SMO_W * sg[dy1] * sg[dx1];
        uint32_t off = SW((uint32_t)(r * 128 + col * 2));
        *(__half2*)(Kh + off) = __halves2half2(__float2half_rn(kx), __float2half_rn(ky));
    }
}

__device__ __forceinline__ void write_probs(int n, const float* u, float inv, float* out_cm) {
    int blk = n >> 6, wi = n & 63;
    char* Bh = (char*)g_Bhi + (size_t)blk * 3072;
    char* Bl = (char*)g_Blo + (size_t)blk * 3072;
    #pragma unroll
    for (int c = 0; c < CC; c++) {
        float o = u[c] * inv;
        out_cm[c * NPIX + n] = o;
        __half h = __float2half_rn(o);
        uint32_t off = SW((uint32_t)(c * 128 + wi * 2));
        *(__half*)(Bh + off) = h;
        *(__half*)(Bl + off) = __float2half_rn(o - __half2float(h));
    }
}

__global__ void k_init(const float* __restrict__ yhat, float* __restrict__ out_cm) {
    int n = blockIdx.x * blockDim.x + threadIdx.x;
    if (n >= NPIX) return;
    float u[CC];
    float mx = -1e30f;
    #pragma unroll
    for (int c = 0; c < CC; c++) {
        float v = yhat[c * NPIX + n];
        g_unary[c * NPIX + n] = v;
        u[c] = v;
        mx = fmaxf(mx, v);
    }
    float s = 0.0f;
    #pragma unroll
    for (int c = 0; c < CC; c++) { u[c] = __expf(u[c] - mx); s += u[c]; }
    write_probs(n, u, 1.0f / s, out_cm);
    int blk = n >> 6, wi = n & 63;
    char* Bh = (char*)g_Bhi + (size_t)blk * 3072;
    char* Bl = (char*)g_Blo + (size_t)blk * 3072;
    #pragma unroll
    for (int c = CC; c < NB; c++) {
        uint32_t off = SW((uint32_t)(c * 128 + wi * 2));
        *(__half*)(Bh + off) = __float2half_rn(0.0f);
        *(__half*)(Bl + off) = __float2half_rn(0.0f);
    }
}

// thread-0 stage fill: 6 bulk copies (2 A-tiles + 4 P-planes)
__device__ __forceinline__ void fill_stage(uint32_t st, int I, int J0, uint32_t mb) {
    #pragma unroll
    for (int k = 0; k < 2; ++k) {
        int J = (k == 0) ? J0 : ((J0 + 1 == NBLK) ? 0 : J0 + 1);
        int lo = (I < J) ? I : J;
        int hi = (I < J) ? J : I;
        size_t tb2 = (size_t)(hi * (hi + 1) / 2 + lo) * 8192;
        bulk_cp(st + A0OF + k * 8192, (char*)g_Khi + tb2, 8192, mb);
        bulk_cp(st + P0HI + k * 6144, (char*)g_Bhi + (size_t)J * 3072, 3072, mb);
        bulk_cp(st + P0LO + k * 6144, (char*)g_Blo + (size_t)J * 3072, 3072, mb);
    }
}

// Owner-computes symmetric GEMM on K_total, 2-term (K*Phi + K*Plo),
// paired L2 schedule, 3-way split-K over J.
__global__ void __launch_bounds__(256, 3) k_gemm_sym5() {
    extern __shared__ char smem[];
    __shared__ uint64_t mbar_s[NSTAGE];
    uint32_t sb = smem_u32(smem);
    int tid = threadIdx.x;
    int lane = tid & 31;
    int w = tid >> 5;
    int r = w & 3;           // 16-row group
    int kh = w >> 2;         // k-half
    int I = blockIdx.x;
    int h = blockIdx.y;
    int Jbase = (48 * h - I + 2 * NBLK) % NBLK;

    uint32_t mb[NSTAGE];
    #pragma unroll
    for (int s = 0; s < NSTAGE; s++) mb[s] = smem_u32(&mbar_s[s]);
    if (tid < NSTAGE) mbar_init(mb[tid], 1);
    __syncthreads();
    if (tid == 0) {
        #pragma unroll
        for (int s = 0; s < NSTAGE; s++) {
            mbar_expect_tx(mb[s], FULLB);
            int J0 = Jbase + 2 * s; if (J0 >= NBLK) J0 -= NBLK;
            fill_stage(sb + s * STAGEB, I, J0, mb[s]);
        }
    }

    // --- precomputed swizzled frag offsets ---
    int arow = r * 16 + (lane & 15);
    int ach = (lane >> 4) + kh * 4;
    uint32_t a_sw[2];
    #pragma unroll
    for (int ks = 0; ks < 2; ks++)
        a_sw[ks] = (uint32_t)(arow * 128 + (((ach + ks * 2) ^ (arow & 7)) << 4));
    int gg = lane >> 3;
    int tch = r * 2 + (gg & 1);
    int trow = kh * 32 + (gg >> 1) * 8 + (lane & 7);
    uint32_t t_sw[2];
    #pragma unroll
    for (int ks = 0; ks < 2; ks++)
        t_sw[ks] = (uint32_t)((trow + ks * 16) * 128 + ((tch ^ (lane & 7)) << 4));
    // B: x4 covers nt0 (lanes 0-15) + nt1 (lanes 16-31); x2 covers nt2
    int l2 = lane & 15;
    int brl = l2 & 7;
    int bch = ((l2 >> 3) & 1) + kh * 4;
    uint32_t b4_sw[2], b2_sw[2];
    #pragma unroll
    for (int ks = 0; ks < 2; ks++) {
        b4_sw[ks] = (uint32_t)((((lane >> 4) * 8) + brl) * 128 + (((bch + ks * 2) ^ brl) << 4));
        b2_sw[ks] = (uint32_t)((16 + brl) * 128 + (((bch + ks * 2) ^ brl) << 4));
    }

    float acc[2][3][4];
    #pragma unroll
    for (int tm = 0; tm < 2; tm++)
        #pragma unroll
        for (int nt = 0; nt < 3; nt++)
            #pragma unroll
            for (int q = 0; q < 4; q++) acc[tm][nt][q] = 0.0f;

    for (int t = 0; t < NSTEP; ++t) {
        int s = t & 1;
        uint32_t st = sb + s * STAGEB;
        mbar_wait(mb[s], (t >> 1) & 1);

        #pragma unroll
        for (int k = 0; k < 2; ++k) {
            int u = 2 * t + k;
            int J = Jbase + u; if (J >= NBLK) J -= NBLK;
            uint32_t Ah = st + A0OF + k * 8192;
            uint32_t Ph = st + P0HI + k * 6144;
            uint32_t Pl = st + P0LO + k * 6144;
            #pragma unroll
            for (int ks = 0; ks < 2; ++ks) {
                uint32_t ah[4];
                if (J >= I) ldsm4(ah[0], ah[1], ah[2], ah[3], Ah + a_sw[ks]);
                else        ldsm4t(ah[0], ah[1], ah[2], ah[3], Ah + t_sw[ks]);
                uint32_t bh[4], bh2[2], bl[4], bl2[2];
                ldsm4(bh[0], bh[1], bh[2], bh[3], Ph + b4_sw[ks]);
                ldsm2(bh2[0], bh2[1], Ph + b2_sw[ks]);
                ldsm4(bl[0], bl[1], bl[2], bl[3], Pl + b4_sw[ks]);
                ldsm2(bl2[0], bl2[1], Pl + b2_sw[ks]);
                hmma(acc[0][0], ah, bh);
                hmma(acc[0][1], ah, bh + 2);
                hmma(acc[0][2], ah, bh2);
                hmma(acc[1][0], ah, bl);
                hmma(acc[1][1], ah, bl + 2);
                hmma(acc[1][2], ah, bl2);
            }
        }
        __syncthreads();
        if (t + NSTAGE < NSTEP && tid == 0) {
            mbar_expect_tx(mb[s], FULLB);
            int J0 = Jbase + 2 * (t + NSTAGE); if (J0 >= NBLK) J0 -= NBLK;
            fill_stage(st, I, J0, mb[s]);
        }
    }

    // epilogue: 2-term sum, k-half reduction via smem, single STG
    float sum_[3][4];
    #pragma unroll
    for (int nt = 0; nt < 3; nt++)
        #pragma unroll
        for (int q = 0; q < 4; q++)
            sum_[nt][q] = acc[0][nt][q] + acc[1][nt][q];

    float* red = (float*)smem;
    int row16 = lane >> 2;
    int cb = (lane & 3) * 2;
    if (kh == 1) {
        #pragma unroll
        for (int nt = 0; nt < 3; ++nt) {
            red[(r * 16 + row16) * 26 + nt * 8 + cb]         = sum_[nt][0];
            red[(r * 16 + row16) * 26 + nt * 8 + cb + 1]     = sum_[nt][1];
            red[(r * 16 + row16 + 8) * 26 + nt * 8 + cb]     = sum_[nt][2];
            red[(r * 16 + row16 + 8) * 26 + nt * 8 + cb + 1] = sum_[nt][3];
        }
    }
    __syncthreads();
    if (kh == 0) {
        float* dst = g_part[h];
        int rg0 = I * 64 + r * 16 + row16;
        #pragma unroll
        for (int nt = 0; nt < 3; ++nt) {
            float s0 = sum_[nt][0] + red[(r * 16 + row16) * 26 + nt * 8 + cb];
            float s1 = sum_[nt][1] + red[(r * 16 + row16) * 26 + nt * 8 + cb + 1];
            float s2 = sum_[nt][2] + red[(r * 16 + row16 + 8) * 26 + nt * 8 + cb];
            float s3 = sum_[nt][3] + red[(r * 16 + row16 + 8) * 26 + nt * 8 + cb + 1];
            *(float2*)&dst[(size_t)rg0 * NB + nt * 8 + cb]       = make_float2(s0, s1);
            *(float2*)&dst[(size_t)(rg0 + 8) * NB + nt * 8 + cb] = make_float2(s2, s3);
        }
    }
}

__global__ void k_combine(const float* __restrict__ mu, float* __restrict__ out_cm) {
    __shared__ float smu[CC * CC];
    for (int i = threadIdx.x; i < CC * CC; i += blockDim.x) smu[i] = mu[i];
    __syncthreads();
    int n = blockIdx.x * blockDim.x + threadIdx.x;
    if (n >= NPIX) return;
    float m[CC];
    #pragma unroll
    for (int c = 0; c < CC; c++)
        m[c] = g_part[0][(size_t)n * NB + c] + g_part[1][(size_t)n * NB + c]
             + g_part[2][(size_t)n * NB + c];
    float u[CC];
    float mx = -1e30f;
    #pragma unroll
    for (int c = 0; c < CC; c++) {
        float s = 0.0f;
        #pragma unroll
        for (int c2 = 0; c2 < CC; c2++) s = fmaf(smu[c2 * CC + c], m[c2], s);
        float v = g_unary[c * NPIX + n] + s;
        g_unary[c * NPIX + n] = v;
        u[c] = v;
        mx = fmaxf(mx, v);
    }
    float s = 0.0f;
    #pragma unroll
    for (int c = 0; c < CC; c++) { u[c] = __expf(u[c] - mx); s += u[c]; }
    write_probs(n, u, 1.0f / s, out_cm);
}

// ---------------- launch ----------------
extern "C" void kernel_launch(void* const* d_in, const int* in_sizes, int n_in,
                              void* d_out, int out_size) {
    const float* x    = (const float*)d_in[0];
    const float* yhat = (const float*)d_in[1];
    const float* mu   = (const float*)d_in[2];
    float* out = (float*)d_out;

    cudaFuncSetAttribute(k_gemm_sym5, cudaFuncAttributeMaxDynamicSharedMemorySize, GEMM_SMEM);

    k_feat<<<(NPIX + 255) / 256, 256>>>(x);
    k_build_t<<<NTILE, 256>>>();
    k_init<<<(NPIX + 255) / 256, 256>>>(yhat, out);

    for (int it = 0; it < CRF_ITERS; ++it) {
        k_gemm_sym5<<<dim3(NBLK, NSPLIT), 256, GEMM_SMEM>>>();
        k_combine<<<(NPIX + 127) / 128, 128>>>(mu, out);
    }
}

// round 11
// speedup vs baseline: 2.2115x; 1.0067x over previous
#include <cuda_runtime.h>
#include <cuda_fp16.h>
#include <cstdint>

#define NPIX 9216
#define HH 96
#define CC 21
#define NB 24
#define CRF_ITERS 5
#define APP_W 10.0f
#define SMO_W 3.0f

#define NBLK 144                        // 64-pixel blocks
#define NTILE (NBLK * (NBLK + 1) / 2)   // 10440 stored upper-tri tiles
#define NSPLIT 3                        // split-K over J-blocks
#define NSTEP 24                        // 48 J-blocks per CTA, 2 per step

// smem stage layout (bytes): 2 A-tiles (hi only) + 2 P-tiles (hi+lo)
#define A0OF 0
#define A1OF 8192
#define P0HI 16384
#define P0LO 19456
#define P1HI 22528
#define P1LO 25600
#define STAGEB 28672
#define NSTAGE 2
#define GEMM_SMEM (NSTAGE * STAGEB)     // 57344
#define FULLB 28672

// XOR swizzle baked into gmem tile layout
#define SW(off) ((off) ^ ((((off) >> 7) & 7) << 4))

// ---------------- persistent device scratch ----------------
static __device__ __half g_Khi[(size_t)NTILE * 4096];  // 85.5 MB, tile-contiguous
static __device__ float  g_feat[6 * NPIX];
static __device__ float  g_gauss[HH];
static __device__ float  g_unary[CC * NPIX];
static __device__ __half g_Bhi[NBLK * NB * 64];        // [block][class][64], swizzled
static __device__ __half g_Blo[NBLK * NB * 64];
static __device__ float  g_part[NSPLIT][(size_t)NPIX * NB];

// ---------------- PTX helpers ----------------
__device__ __forceinline__ uint32_t smem_u32(const void* p) {
    uint32_t a;
    asm("{ .reg .u64 t; cvta.to.shared.u64 t, %1; cvt.u32.u64 %0, t; }" : "=r"(a) : "l"(p));
    return a;
}
__device__ __forceinline__ void mbar_init(uint32_t a, uint32_t c) {
    asm volatile("mbarrier.init.shared.b64 [%0], %1;" :: "r"(a), "r"(c) : "memory");
}
__device__ __forceinline__ void mbar_expect_tx(uint32_t a, uint32_t bytes) {
    asm volatile("mbarrier.arrive.expect_tx.shared.b64 _, [%0], %1;" :: "r"(a), "r"(bytes) : "memory");
}
__device__ __forceinline__ void mbar_wait(uint32_t mbar, uint32_t parity) {
    asm volatile(
        "{\n\t.reg .pred P1;\n\t"
        "WL%=:\n\t"
        "mbarrier.try_wait.parity.shared.b64 P1, [%0], %1;\n\t"
        "@!P1 bra WL%=;\n\t}"
        :: "r"(mbar), "r"(parity) : "memory");
}
__device__ __forceinline__ void bulk_cp(uint32_t dst, const void* src, uint32_t bytes, uint32_t mbar) {
    asm volatile(
        "cp.async.bulk.shared::cluster.global.mbarrier::complete_tx::bytes [%0], [%1], %2, [%3];"
        :: "r"(dst), "l"(src), "r"(bytes), "r"(mbar) : "memory");
}
// evict_last variant: K tiles are re-read every iteration and fit in L2 (85.5 MB < 126 MB)
__device__ __forceinline__ void bulk_cp_ll(uint32_t dst, const void* src, uint32_t bytes, uint32_t mbar) {
    asm volatile(
        "{\n\t.reg .b64 pol;\n\t"
        "createpolicy.fractional.L2::evict_last.b64 pol, 1.0;\n\t"
        "cp.async.bulk.shared::cluster.global.mbarrier::complete_tx::bytes.L2::cache_hint"
        " [%0], [%1], %2, [%3], pol;\n\t}"
        :: "r"(dst), "l"(src), "r"(bytes), "r"(mbar) : "memory");
}
__device__ __forceinline__ void ldsm4(uint32_t& r0, uint32_t& r1, uint32_t& r2, uint32_t& r3, uint32_t addr) {
    asm volatile("ldmatrix.sync.aligned.m8n8.x4.shared.b16 {%0,%1,%2,%3}, [%4];"
        : "=r"(r0), "=r"(r1), "=r"(r2), "=r"(r3) : "r"(addr));
}
__device__ __forceinline__ void ldsm4t(uint32_t& r0, uint32_t& r1, uint32_t& r2, uint32_t& r3, uint32_t addr) {
    asm volatile("ldmatrix.sync.aligned.m8n8.x4.trans.shared.b16 {%0,%1,%2,%3}, [%4];"
        : "=r"(r0), "=r"(r1), "=r"(r2), "=r"(r3) : "r"(addr));
}
__device__ __forceinline__ void ldsm2(uint32_t& r0, uint32_t& r1, uint32_t addr) {
    asm volatile("ldmatrix.sync.aligned.m8n8.x2.shared.b16 {%0,%1}, [%2];"
        : "=r"(r0), "=r"(r1) : "r"(addr));
}
__device__ __forceinline__ void hmma(float* c, const uint32_t* a, const uint32_t* b) {
    asm volatile(
        "mma.sync.aligned.m16n8k16.row.col.f32.f16.f16.f32 "
        "{%0,%1,%2,%3}, {%4,%5,%6,%7}, {%8,%9}, {%0,%1,%2,%3};"
        : "+f"(c[0]), "+f"(c[1]), "+f"(c[2]), "+f"(c[3])
        : "r"(a[0]), "r"(a[1]), "r"(a[2]), "r"(a[3]), "r"(b[0]), "r"(b[1]));
}
__device__ __forceinline__ void tri_decode(int bid, int& lo, int& hi) {
    int r = (int)((sqrtf(8.0f * (float)bid + 1.0f) - 1.0f) * 0.5f);
    while ((r + 1) * (r + 2) / 2 <= bid) ++r;
    while (r * (r + 1) / 2 > bid) --r;
    hi = r;
    lo = bid - r * (r + 1) / 2;
}

// ---------------- kernels ----------------

__global__ void k_feat(const float* __restrict__ x) {
    int n = blockIdx.x * blockDim.x + threadIdx.x;
    if (n >= NPIX) return;
    int y = n / HH, xc = n % HH;
    float f0 = (float)y  * (1.0f / 30.0f);
    float f1 = (float)xc * (1.0f / 30.0f);
    float f2 = x[n]            * 10.0f;
    float f3 = x[NPIX + n]     * 10.0f;
    float f4 = x[2 * NPIX + n] * 10.0f;
    float sq = f0*f0 + f1*f1 + f2*f2 + f3*f3 + f4*f4;
    g_feat[n]            = sq;
    g_feat[NPIX     + n] = f0;
    g_feat[2*NPIX   + n] = f1;
    g_feat[3*NPIX   + n] = f2;
    g_feat[4*NPIX   + n] = f3;
    g_feat[5*NPIX   + n] = f4;
    if (n < HH) g_gauss[n] = expf(-(float)(n * n) * (1.0f / 18.0f));
}

// Upper-tri build of K_total = APP_W*K_bi + SMO_W*K_sm into tile-contiguous
// swizzled fp16 layout. K_sm(a,b) = g_gauss[|dy|]*g_gauss[|dx|] (separable table).
__global__ void __launch_bounds__(256) k_build_t() {
    __shared__ float sg[HH];
    int ta, tb;
    tri_decode(blockIdx.x, ta, tb);        // ta <= tb
    size_t tbase = (size_t)blockIdx.x * 8192;
    int tid = threadIdx.x;
    if (tid < HH) sg[tid] = g_gauss[tid];
    __syncthreads();
    int r  = tid >> 2;
    int cq = (tid & 3) * 16;

    int a = ta * 64 + r;
    int ya = a / HH, xa = a % HH;
    float sqa = g_feat[a];
    float a0 = g_feat[NPIX   + a];
    float a1 = g_feat[2*NPIX + a];
    float a2 = g_feat[3*NPIX + a];
    float a3 = g_feat[4*NPIX + a];
    float a4 = g_feat[5*NPIX + a];

    char* Kh = (char*)g_Khi + tbase;
    #pragma unroll
    for (int q = 0; q < 8; ++q) {
        int col = cq + 2 * q;
        int b = tb * 64 + col;
        float2 sqb = *(const float2*)&g_feat[b];
        float2 b0  = *(const float2*)&g_feat[NPIX   + b];
        float2 b1  = *(const float2*)&g_feat[2*NPIX + b];
        float2 b2  = *(const float2*)&g_feat[3*NPIX + b];
        float2 b3  = *(const float2*)&g_feat[4*NPIX + b];
        float2 b4  = *(const float2*)&g_feat[5*NPIX + b];
        float dotx = a0*b0.x + a1*b1.x + a2*b2.x + a3*b3.x + a4*b4.x;
        float doty = a0*b0.y + a1*b1.y + a2*b2.y + a3*b3.y + a4*b4.y;
        int yb0 = b / HH, xb0 = b % HH;
        int yb1 = (b + 1) / HH, xb1 = (b + 1) % HH;
        int dy0 = ya - yb0; dy0 = (dy0 < 0) ? -dy0 : dy0;
        int dx0 = xa - xb0; dx0 = (dx0 < 0) ? -dx0 : dx0;
        int dy1 = ya - yb1; dy1 = (dy1 < 0) ? -dy1 : dy1;
        int dx1 = xa - xb1; dx1 = (dx1 < 0) ? -dx1 : dx1;
        float kx = APP_W * __expf(-0.5f * fmaxf(sqa + sqb.x - 2.0f * dotx, 0.0f))
                 + SMO_W * sg[dy0] * sg[dx0];
        float ky = APP_W * __expf(-0.5f * fmaxf(sqa + sqb.y - 2.0f * doty, 0.0f))
                 + SMO_W * sg[dy1] * sg[dx1];
        uint32_t off = SW((uint32_t)(r * 128 + col * 2));
        *(__half2*)(Kh + off) = __halves2half2(__float2half_rn(kx), __float2half_rn(ky));
    }
}

__device__ __forceinline__ void write_probs(int n, const float* u, float inv, float* out_cm) {
    int blk = n >> 6, wi = n & 63;
    char* Bh = (char*)g_Bhi + (size_t)blk * 3072;
    char* Bl = (char*)g_Blo + (size_t)blk * 3072;
    #pragma unroll
    for (int c = 0; c < CC; c++) {
        float o = u[c] * inv;
        out_cm[c * NPIX + n] = o;
        __half h = __float2half_rn(o);
        uint32_t off = SW((uint32_t)(c * 128 + wi * 2));
        *(__half*)(Bh + off) = h;
        *(__half*)(Bl + off) = __float2half_rn(o - __half2float(h));
    }
}

__global__ void k_init(const float* __restrict__ yhat, float* __restrict__ out_cm) {
    int n = blockIdx.x * blockDim.x + threadIdx.x;
    if (n >= NPIX) return;
    float u[CC];
    float mx = -1e30f;
    #pragma unroll
    for (int c = 0; c < CC; c++) {
        float v = yhat[c * NPIX + n];
        g_unary[c * NPIX + n] = v;
        u[c] = v;
        mx = fmaxf(mx, v);
    }
    float s = 0.0f;
    #pragma unroll
    for (int c = 0; c < CC; c++) { u[c] = __expf(u[c] - mx); s += u[c]; }
    write_probs(n, u, 1.0f / s, out_cm);
    int blk = n >> 6, wi = n & 63;
    char* Bh = (char*)g_Bhi + (size_t)blk * 3072;
    char* Bl = (char*)g_Blo + (size_t)blk * 3072;
    #pragma unroll
    for (int c = CC; c < NB; c++) {
        uint32_t off = SW((uint32_t)(c * 128 + wi * 2));
        *(__half*)(Bh + off) = __float2half_rn(0.0f);
        *(__half*)(Bl + off) = __float2half_rn(0.0f);
    }
}

// thread-0 stage fill: 6 bulk copies (2 A-tiles evict_last + 4 P-planes)
__device__ __forceinline__ void fill_stage(uint32_t st, int I, int J0, uint32_t mb) {
    #pragma unroll
    for (int k = 0; k < 2; ++k) {
        int J = (k == 0) ? J0 : ((J0 + 1 == NBLK) ? 0 : J0 + 1);
        int lo = (I < J) ? I : J;
        int hi = (I < J) ? J : I;
        size_t tb2 = (size_t)(hi * (hi + 1) / 2 + lo) * 8192;
        bulk_cp_ll(st + A0OF + k * 8192, (char*)g_Khi + tb2, 8192, mb);
        bulk_cp(st + P0HI + k * 6144, (char*)g_Bhi + (size_t)J * 3072, 3072, mb);
        bulk_cp(st + P0LO + k * 6144, (char*)g_Blo + (size_t)J * 3072, 3072, mb);
    }
}

// Owner-computes symmetric GEMM on K_total, 2-term (K*Phi + K*Plo),
// paired L2 schedule, 3-way split-K over J.
__global__ void __launch_bounds__(256, 3) k_gemm_sym5() {
    extern __shared__ char smem[];
    __shared__ uint64_t mbar_s[NSTAGE];
    uint32_t sb = smem_u32(smem);
    int tid = threadIdx.x;
    int lane = tid & 31;
    int w = tid >> 5;
    int r = w & 3;           // 16-row group
    int kh = w >> 2;         // k-half
    int I = blockIdx.x;
    int h = blockIdx.y;
    int Jbase = (48 * h - I + 2 * NBLK) % NBLK;

    uint32_t mb[NSTAGE];
    #pragma unroll
    for (int s = 0; s < NSTAGE; s++) mb[s] = smem_u32(&mbar_s[s]);
    if (tid < NSTAGE) mbar_init(mb[tid], 1);
    __syncthreads();
    if (tid == 0) {
        #pragma unroll
        for (int s = 0; s < NSTAGE; s++) {
            mbar_expect_tx(mb[s], FULLB);
            int J0 = Jbase + 2 * s; if (J0 >= NBLK) J0 -= NBLK;
            fill_stage(sb + s * STAGEB, I, J0, mb[s]);
        }
    }

    // --- precomputed swizzled frag offsets ---
    int arow = r * 16 + (lane & 15);
    int ach = (lane >> 4) + kh * 4;
    uint32_t a_sw[2];
    #pragma unroll
    for (int ks = 0; ks < 2; ks++)
        a_sw[ks] = (uint32_t)(arow * 128 + (((ach + ks * 2) ^ (arow & 7)) << 4));
    int gg = lane >> 3;
    int tch = r * 2 + (gg & 1);
    int trow = kh * 32 + (gg >> 1) * 8 + (lane & 7);
    uint32_t t_sw[2];
    #pragma unroll
    for (int ks = 0; ks < 2; ks++)
        t_sw[ks] = (uint32_t)((trow + ks * 16) * 128 + ((tch ^ (lane & 7)) << 4));
    // B: x4 covers nt0 (lanes 0-15) + nt1 (lanes 16-31); x2 covers nt2
    int l2 = lane & 15;
    int brl = l2 & 7;
    int bch = ((l2 >> 3) & 1) + kh * 4;
    uint32_t b4_sw[2], b2_sw[2];
    #pragma unroll
    for (int ks = 0; ks < 2; ks++) {
        b4_sw[ks] = (uint32_t)((((lane >> 4) * 8) + brl) * 128 + (((bch + ks * 2) ^ brl) << 4));
        b2_sw[ks] = (uint32_t)((16 + brl) * 128 + (((bch + ks * 2) ^ brl) << 4));
    }

    float acc[2][3][4];
    #pragma unroll
    for (int tm = 0; tm < 2; tm++)
        #pragma unroll
        for (int nt = 0; nt < 3; nt++)
            #pragma unroll
            for (int q = 0; q < 4; q++) acc[tm][nt][q] = 0.0f;

    for (int t = 0; t < NSTEP; ++t) {
        int s = t & 1;
        uint32_t st = sb + s * STAGEB;
        mbar_wait(mb[s], (t >> 1) & 1);

        #pragma unroll
        for (int k = 0; k < 2; ++k) {
            int u = 2 * t + k;
            int J = Jbase + u; if (J >= NBLK) J -= NBLK;
            uint32_t Ah = st + A0OF + k * 8192;
            uint32_t Ph = st + P0HI + k * 6144;
            uint32_t Pl = st + P0LO + k * 6144;
            #pragma unroll
            for (int ks = 0; ks < 2; ++ks) {
                uint32_t ah[4];
                if (J >= I) ldsm4(ah[0], ah[1], ah[2], ah[3], Ah + a_sw[ks]);
                else        ldsm4t(ah[0], ah[1], ah[2], ah[3], Ah + t_sw[ks]);
                uint32_t bh[4], bh2[2], bl[4], bl2[2];
                ldsm4(bh[0], bh[1], bh[2], bh[3], Ph + b4_sw[ks]);
                ldsm2(bh2[0], bh2[1], Ph + b2_sw[ks]);
                ldsm4(bl[0], bl[1], bl[2], bl[3], Pl + b4_sw[ks]);
                ldsm2(bl2[0], bl2[1], Pl + b2_sw[ks]);
                hmma(acc[0][0], ah, bh);
                hmma(acc[0][1], ah, bh + 2);
                hmma(acc[0][2], ah, bh2);
                hmma(acc[1][0], ah, bl);
                hmma(acc[1][1], ah, bl + 2);
                hmma(acc[1][2], ah, bl2);
            }
        }
        __syncthreads();
        if (t + NSTAGE < NSTEP && tid == 0) {
            mbar_expect_tx(mb[s], FULLB);
            int J0 = Jbase + 2 * (t + NSTAGE); if (J0 >= NBLK) J0 -= NBLK;
            fill_stage(st, I, J0, mb[s]);
        }
    }

    // epilogue: 2-term sum, k-half reduction via smem, single STG
    float sum_[3][4];
    #pragma unroll
    for (int nt = 0; nt < 3; nt++)
        #pragma unroll
        for (int q = 0; q < 4; q++)
            sum_[nt][q] = acc[0][nt][q] + acc[1][nt][q];

    float* red = (float*)smem;
    int row16 = lane >> 2;
    int cb = (lane & 3) * 2;
    if (kh == 1) {
        #pragma unroll
        for (int nt = 0; nt < 3; ++nt) {
            red[(r * 16 + row16) * 26 + nt * 8 + cb]         = sum_[nt][0];
            red[(r * 16 + row16) * 26 + nt * 8 + cb + 1]     = sum_[nt][1];
            red[(r * 16 + row16 + 8) * 26 + nt * 8 + cb]     = sum_[nt][2];
            red[(r * 16 + row16 + 8) * 26 + nt * 8 + cb + 1] = sum_[nt][3];
        }
    }
    __syncthreads();
    if (kh == 0) {
        float* dst = g_part[h];
        int rg0 = I * 64 + r * 16 + row16;
        #pragma unroll
        for (int nt = 0; nt < 3; ++nt) {
            float s0 = sum_[nt][0] + red[(r * 16 + row16) * 26 + nt * 8 + cb];
            float s1 = sum_[nt][1] + red[(r * 16 + row16) * 26 + nt * 8 + cb + 1];
            float s2 = sum_[nt][2] + red[(r * 16 + row16 + 8) * 26 + nt * 8 + cb];
            float s3 = sum_[nt][3] + red[(r * 16 + row16 + 8) * 26 + nt * 8 + cb + 1];
            *(float2*)&dst[(size_t)rg0 * NB + nt * 8 + cb]       = make_float2(s0, s1);
            *(float2*)&dst[(size_t)(rg0 + 8) * NB + nt * 8 + cb] = make_float2(s2, s3);
        }
    }
}

// 144 blocks x 64 threads (full-chip spread), float4 part loads.
__global__ void __launch_bounds__(64) k_combine(const float* __restrict__ mu,
                                                float* __restrict__ out_cm) {
    __shared__ float smu[CC * CC];
    for (int i = threadIdx.x; i < CC * CC; i += 64) smu[i] = mu[i];
    __syncthreads();
    int n = blockIdx.x * 64 + threadIdx.x;   // NPIX = 144*64 exactly
    float m2[NB];
    const float4* p0 = (const float4*)&g_part[0][(size_t)n * NB];
    const float4* p1 = (const float4*)&g_part[1][(size_t)n * NB];
    const float4* p2 = (const float4*)&g_part[2][(size_t)n * NB];
    #pragma unroll
    for (int q = 0; q < 6; q++) {
        float4 a = p0[q], b = p1[q], c = p2[q];
        m2[4*q]     = a.x + b.x + c.x;
        m2[4*q + 1] = a.y + b.y + c.y;
        m2[4*q + 2] = a.z + b.z + c.z;
        m2[4*q + 3] = a.w + b.w + c.w;
    }
    float u[CC];
    float mx = -1e30f;
    #pragma unroll
    for (int c = 0; c < CC; c++) {
        float s = 0.0f;
        #pragma unroll
        for (int c2 = 0; c2 < CC; c2++) s = fmaf(smu[c2 * CC + c], m2[c2], s);
        float v = g_unary[c * NPIX + n] + s;
        g_unary[c * NPIX + n] = v;
        u[c] = v;
        mx = fmaxf(mx, v);
    }
    float s = 0.0f;
    #pragma unroll
    for (int c = 0; c < CC; c++) { u[c] = __expf(u[c] - mx); s += u[c]; }
    write_probs(n, u, 1.0f / s, out_cm);
}

// ---------------- launch ----------------
extern "C" void kernel_launch(void* const* d_in, const int* in_sizes, int n_in,
                              void* d_out, int out_size) {
    const float* x    = (const float*)d_in[0];
    const float* yhat = (const float*)d_in[1];
    const float* mu   = (const float*)d_in[2];
    float* out = (float*)d_out;

    cudaFuncSetAttribute(k_gemm_sym5, cudaFuncAttributeMaxDynamicSharedMemorySize, GEMM_SMEM);

    k_feat<<<(NPIX + 255) / 256, 256>>>(x);
    k_build_t<<<NTILE, 256>>>();
    k_init<<<(NPIX + 255) / 256, 256>>>(yhat, out);

    for (int it = 0; it < CRF_ITERS; ++it) {
        k_gemm_sym5<<<dim3(NBLK, NSPLIT), 256, GEMM_SMEM>>>();
        k_combine<<<NBLK, 64>>>(mu, out);
    }
}

// round 12
// speedup vs baseline: 2.2450x; 1.0152x over previous
#include <cuda_runtime.h>
#include <cuda_fp16.h>
#include <cstdint>

#define NPIX 9216
#define HH 96
#define CC 21
#define NB 24
#define CRF_ITERS 5
#define APP_W 10.0f
#define SMO_W 3.0f

#define NBLK 144                        // 64-pixel blocks
#define NTILE (NBLK * (NBLK + 1) / 2)   // 10440 stored upper-tri tiles
#define NSPLIT 3                        // split-K over J-blocks
#define NSTEP 24                        // 48 J-blocks per CTA, 2 per step

// smem stage layout (bytes): 2 A-tiles (hi only) + 2 P-tiles (hi+lo)
#define A0OF 0
#define A1OF 8192
#define P0HI 16384
#define P0LO 19456
#define P1HI 22528
#define P1LO 25600
#define STAGEB 28672
#define NSTAGE 2
#define GEMM_SMEM (NSTAGE * STAGEB)     // 57344
#define FULLB 28672

// XOR swizzle baked into gmem tile layout
#define SW(off) ((off) ^ ((((off) >> 7) & 7) << 4))

// ---------------- persistent device scratch ----------------
static __device__ __half g_Khi[(size_t)NTILE * 4096];  // 85.5 MB, tile-contiguous
static __device__ float  g_feat[6 * NPIX];
static __device__ float  g_gauss[HH];
static __device__ float  g_unary[CC * NPIX];
static __device__ __half g_Bhi[NBLK * NB * 64];        // [block][class][64], swizzled
static __device__ __half g_Blo[NBLK * NB * 64];
static __device__ float  g_part[NSPLIT][(size_t)NPIX * NB];

// ---------------- PTX helpers ----------------
__device__ __forceinline__ uint32_t smem_u32(const void* p) {
    uint32_t a;
    asm("{ .reg .u64 t; cvta.to.shared.u64 t, %1; cvt.u32.u64 %0, t; }" : "=r"(a) : "l"(p));
    return a;
}
__device__ __forceinline__ void mbar_init(uint32_t a, uint32_t c) {
    asm volatile("mbarrier.init.shared.b64 [%0], %1;" :: "r"(a), "r"(c) : "memory");
}
__device__ __forceinline__ void mbar_expect_tx(uint32_t a, uint32_t bytes) {
    asm volatile("mbarrier.arrive.expect_tx.shared.b64 _, [%0], %1;" :: "r"(a), "r"(bytes) : "memory");
}
__device__ __forceinline__ void mbar_wait(uint32_t mbar, uint32_t parity) {
    asm volatile(
        "{\n\t.reg .pred P1;\n\t"
        "WL%=:\n\t"
        "mbarrier.try_wait.parity.shared.b64 P1, [%0], %1;\n\t"
        "@!P1 bra WL%=;\n\t}"
        :: "r"(mbar), "r"(parity) : "memory");
}
__device__ __forceinline__ void bulk_cp(uint32_t dst, const void* src, uint32_t bytes, uint32_t mbar) {
    asm volatile(
        "cp.async.bulk.shared::cluster.global.mbarrier::complete_tx::bytes [%0], [%1], %2, [%3];"
        :: "r"(dst), "l"(src), "r"(bytes), "r"(mbar) : "memory");
}
// evict_last hint on K tiles (neutral so far; kept to bias eviction toward P/part traffic)
__device__ __forceinline__ void bulk_cp_ll(uint32_t dst, const void* src, uint32_t bytes, uint32_t mbar) {
    asm volatile(
        "{\n\t.reg .b64 pol;\n\t"
        "createpolicy.fractional.L2::evict_last.b64 pol, 1.0;\n\t"
        "cp.async.bulk.shared::cluster.global.mbarrier::complete_tx::bytes.L2::cache_hint"
        " [%0], [%1], %2, [%3], pol;\n\t}"
        :: "r"(dst), "l"(src), "r"(bytes), "r"(mbar) : "memory");
}
__device__ __forceinline__ void ldsm4(uint32_t& r0, uint32_t& r1, uint32_t& r2, uint32_t& r3, uint32_t addr) {
    asm volatile("ldmatrix.sync.aligned.m8n8.x4.shared.b16 {%0,%1,%2,%3}, [%4];"
        : "=r"(r0), "=r"(r1), "=r"(r2), "=r"(r3) : "r"(addr));
}
__device__ __forceinline__ void ldsm4t(uint32_t& r0, uint32_t& r1, uint32_t& r2, uint32_t& r3, uint32_t addr) {
    asm volatile("ldmatrix.sync.aligned.m8n8.x4.trans.shared.b16 {%0,%1,%2,%3}, [%4];"
        : "=r"(r0), "=r"(r1), "=r"(r2), "=r"(r3) : "r"(addr));
}
__device__ __forceinline__ void hmma(float* c, const uint32_t* a, const uint32_t* b) {
    asm volatile(
        "mma.sync.aligned.m16n8k16.row.col.f32.f16.f16.f32 "
        "{%0,%1,%2,%3}, {%4,%5,%6,%7}, {%8,%9}, {%0,%1,%2,%3};"
        : "+f"(c[0]), "+f"(c[1]), "+f"(c[2]), "+f"(c[3])
        : "r"(a[0]), "r"(a[1]), "r"(a[2]), "r"(a[3]), "r"(b[0]), "r"(b[1]));
}
__device__ __forceinline__ void tri_decode(int bid, int& lo, int& hi) {
    int r = (int)((sqrtf(8.0f * (float)bid + 1.0f) - 1.0f) * 0.5f);
    while ((r + 1) * (r + 2) / 2 <= bid) ++r;
    while (r * (r + 1) / 2 > bid) --r;
    hi = r;
    lo = bid - r * (r + 1) / 2;
}

// ---------------- kernels ----------------

__global__ void k_feat(const float* __restrict__ x) {
    int n = blockIdx.x * blockDim.x + threadIdx.x;
    if (n >= NPIX) return;
    int y = n / HH, xc = n % HH;
    float f0 = (float)y  * (1.0f / 30.0f);
    float f1 = (float)xc * (1.0f / 30.0f);
    float f2 = x[n]            * 10.0f;
    float f3 = x[NPIX + n]     * 10.0f;
    float f4 = x[2 * NPIX + n] * 10.0f;
    float sq = f0*f0 + f1*f1 + f2*f2 + f3*f3 + f4*f4;
    g_feat[n]            = sq;
    g_feat[NPIX     + n] = f0;
    g_feat[2*NPIX   + n] = f1;
    g_feat[3*NPIX   + n] = f2;
    g_feat[4*NPIX   + n] = f3;
    g_feat[5*NPIX   + n] = f4;
    if (n < HH) g_gauss[n] = expf(-(float)(n * n) * (1.0f / 18.0f));
}

// Upper-tri build of K_total = APP_W*K_bi + SMO_W*K_sm into tile-contiguous
// swizzled fp16 layout. K_sm(a,b) = g_gauss[|dy|]*g_gauss[|dx|] (separable table).
__global__ void __launch_bounds__(256) k_build_t() {
    __shared__ float sg[HH];
    int ta, tb;
    tri_decode(blockIdx.x, ta, tb);        // ta <= tb
    size_t tbase = (size_t)blockIdx.x * 8192;
    int tid = threadIdx.x;
    if (tid < HH) sg[tid] = g_gauss[tid];
    __syncthreads();
    int r  = tid >> 2;
    int cq = (tid & 3) * 16;

    int a = ta * 64 + r;
    int ya = a / HH, xa = a % HH;
    float sqa = g_feat[a];
    float a0 = g_feat[NPIX   + a];
    float a1 = g_feat[2*NPIX + a];
    float a2 = g_feat[3*NPIX + a];
    float a3 = g_feat[4*NPIX + a];
    float a4 = g_feat[5*NPIX + a];

    char* Kh = (char*)g_Khi + tbase;
    #pragma unroll
    for (int q = 0; q < 8; ++q) {
        int col = cq + 2 * q;
        int b = tb * 64 + col;
        float2 sqb = *(const float2*)&g_feat[b];
        float2 b0  = *(const float2*)&g_feat[NPIX   + b];
        float2 b1  = *(const float2*)&g_feat[2*NPIX + b];
        float2 b2  = *(const float2*)&g_feat[3*NPIX + b];
        float2 b3  = *(const float2*)&g_feat[4*NPIX + b];
        float2 b4  = *(const float2*)&g_feat[5*NPIX + b];
        float dotx = a0*b0.x + a1*b1.x + a2*b2.x + a3*b3.x + a4*b4.x;
        float doty = a0*b0.y + a1*b1.y + a2*b2.y + a3*b3.y + a4*b4.y;
        int yb0 = b / HH, xb0 = b % HH;
        int yb1 = (b + 1) / HH, xb1 = (b + 1) % HH;
        int dy0 = ya - yb0; dy0 = (dy0 < 0) ? -dy0 : dy0;
        int dx0 = xa - xb0; dx0 = (dx0 < 0) ? -dx0 : dx0;
        int dy1 = ya - yb1; dy1 = (dy1 < 0) ? -dy1 : dy1;
        int dx1 = xa - xb1; dx1 = (dx1 < 0) ? -dx1 : dx1;
        float kx = APP_W * __expf(-0.5f * fmaxf(sqa + sqb.x - 2.0f * dotx, 0.0f))
                 + SMO_W * sg[dy0] * sg[dx0];
        float ky = APP_W * __expf(-0.5f * fmaxf(sqa + sqb.y - 2.0f * doty, 0.0f))
                 + SMO_W * sg[dy1] * sg[dx1];
        uint32_t off = SW((uint32_t)(r * 128 + col * 2));
        *(__half2*)(Kh + off) = __halves2half2(__float2half_rn(kx), __float2half_rn(ky));
    }
}

__device__ __forceinline__ void write_probs(int n, const float* u, float inv, float* out_cm) {
    int blk = n >> 6, wi = n & 63;
    char* Bh = (char*)g_Bhi + (size_t)blk * 3072;
    char* Bl = (char*)g_Blo + (size_t)blk * 3072;
    #pragma unroll
    for (int c = 0; c < CC; c++) {
        float o = u[c] * inv;
        out_cm[c * NPIX + n] = o;
        __half h = __float2half_rn(o);
        uint32_t off = SW((uint32_t)(c * 128 + wi * 2));
        *(__half*)(Bh + off) = h;
        *(__half*)(Bl + off) = __float2half_rn(o - __half2float(h));
    }
}

__global__ void k_init(const float* __restrict__ yhat, float* __restrict__ out_cm) {
    int n = blockIdx.x * blockDim.x + threadIdx.x;
    if (n >= NPIX) return;
    float u[CC];
    float mx = -1e30f;
    #pragma unroll
    for (int c = 0; c < CC; c++) {
        float v = yhat[c * NPIX + n];
        g_unary[c * NPIX + n] = v;
        u[c] = v;
        mx = fmaxf(mx, v);
    }
    float s = 0.0f;
    #pragma unroll
    for (int c = 0; c < CC; c++) { u[c] = __expf(u[c] - mx); s += u[c]; }
    write_probs(n, u, 1.0f / s, out_cm);
    int blk = n >> 6, wi = n & 63;
    char* Bh = (char*)g_Bhi + (size_t)blk * 3072;
    char* Bl = (char*)g_Blo + (size_t)blk * 3072;
    #pragma unroll
    for (int c = CC; c < NB; c++) {
        uint32_t off = SW((uint32_t)(c * 128 + wi * 2));
        *(__half*)(Bh + off) = __float2half_rn(0.0f);
        *(__half*)(Bl + off) = __float2half_rn(0.0f);
    }
}

// thread-0 stage fill: slot k=0 holds Ja, slot k=1 holds Jb.
__device__ __forceinline__ void fill_stage(uint32_t st, int I, int Ja, int Jb, uint32_t mb) {
    #pragma unroll
    for (int k = 0; k < 2; ++k) {
        int J = (k == 0) ? Ja : Jb;
        int lo = (I < J) ? I : J;
        int hi = (I < J) ? J : I;
        size_t tb2 = (size_t)(hi * (hi + 1) / 2 + lo) * 8192;
        bulk_cp_ll(st + A0OF + k * 8192, (char*)g_Khi + tb2, 8192, mb);
        bulk_cp(st + P0HI + k * 6144, (char*)g_Bhi + (size_t)J * 3072, 3072, mb);
        bulk_cp(st + P0LO + k * 6144, (char*)g_Blo + (size_t)J * 3072, 3072, mb);
    }
}

// Owner-computes symmetric GEMM on K_total, 2-term (K*Phi + K*Plo),
// paired L2 schedule, 3-way split-K, serpentine J-order across iterations.
__global__ void __launch_bounds__(256, 3) k_gemm_sym6(int rev) {
    extern __shared__ char smem[];
    __shared__ uint64_t mbar_s[NSTAGE];
    uint32_t sb = smem_u32(smem);
    int tid = threadIdx.x;
    int lane = tid & 31;
    int w = tid >> 5;
    int r = w & 3;           // 16-row group
    int kh = w >> 2;         // k-half
    int I = blockIdx.x;
    int h = blockIdx.y;
    int Jbase = (48 * h - I + 2 * NBLK) % NBLK;

    // seq(u): serpentine — odd iterations sweep J in reverse order.
    #define SEQ(u) ({ int v_ = rev ? (2 * NSTEP - 1 - (u)) : (u); \
                      int J_ = Jbase + v_; if (J_ >= NBLK) J_ -= NBLK; J_; })

    uint32_t mb[NSTAGE];
    #pragma unroll
    for (int s = 0; s < NSTAGE; s++) mb[s] = smem_u32(&mbar_s[s]);
    if (tid < NSTAGE) mbar_init(mb[tid], 1);
    __syncthreads();
    if (tid == 0) {
        #pragma unroll
        for (int s = 0; s < NSTAGE; s++) {
            mbar_expect_tx(mb[s], FULLB);
            fill_stage(sb + s * STAGEB, I, SEQ(2 * s), SEQ(2 * s + 1), mb[s]);
        }
    }

    // --- precomputed swizzled frag offsets ---
    int arow = r * 16 + (lane & 15);
    int ach = (lane >> 4) + kh * 4;
    uint32_t a_sw[2];
    #pragma unroll
    for (int ks = 0; ks < 2; ks++)
        a_sw[ks] = (uint32_t)(arow * 128 + (((ach + ks * 2) ^ (arow & 7)) << 4));
    int gg = lane >> 3;
    int tch = r * 2 + (gg & 1);
    int trow = kh * 32 + (gg >> 1) * 8 + (lane & 7);
    uint32_t t_sw[2];
    #pragma unroll
    for (int ks = 0; ks < 2; ks++)
        t_sw[ks] = (uint32_t)((trow + ks * 16) * 128 + ((tch ^ (lane & 7)) << 4));
    // B: x4 #1 covers Phi nt0+nt1; x4 #2 covers Plo nt0+nt1;
    //    x4 #3 (packed) covers Phi-nt2 (lanes 0-15) + Plo-nt2 (lanes 16-31)
    int l2 = lane & 15;
    int brl = l2 & 7;
    int bch = ((l2 >> 3) & 1) + kh * 4;
    uint32_t b4_sw[2], b2p_sw[2];
    #pragma unroll
    for (int ks = 0; ks < 2; ks++) {
        b4_sw[ks]  = (uint32_t)((((lane >> 4) * 8) + brl) * 128 + (((bch + ks * 2) ^ brl) << 4));
        b2p_sw[ks] = (uint32_t)((lane < 16 ? 0 : 3072) + (16 + brl) * 128
                                + (((bch + ks * 2) ^ brl) << 4));
    }

    float acc[2][3][4];
    #pragma unroll
    for (int tm = 0; tm < 2; tm++)
        #pragma unroll
        for (int nt = 0; nt < 3; nt++)
            #pragma unroll
            for (int q = 0; q < 4; q++) acc[tm][nt][q] = 0.0f;

    for (int t = 0; t < NSTEP; ++t) {
        int s = t & 1;
        uint32_t st = sb + s * STAGEB;
        mbar_wait(mb[s], (t >> 1) & 1);

        #pragma unroll
        for (int k = 0; k < 2; ++k) {
            int J = SEQ(2 * t + k);
            uint32_t Ah = st + A0OF + k * 8192;
            uint32_t Ph = st + P0HI + k * 6144;
            #pragma unroll
            for (int ks = 0; ks < 2; ++ks) {
                uint32_t ah[4];
                if (J >= I) ldsm4(ah[0], ah[1], ah[2], ah[3], Ah + a_sw[ks]);
                else        ldsm4t(ah[0], ah[1], ah[2], ah[3], Ah + t_sw[ks]);
                uint32_t bh[4], bl[4], b2[4];
                ldsm4(bh[0], bh[1], bh[2], bh[3], Ph + b4_sw[ks]);
                ldsm4(bl[0], bl[1], bl[2], bl[3], Ph + 3072 + b4_sw[ks]);
                ldsm4(b2[0], b2[1], b2[2], b2[3], Ph + b2p_sw[ks]);
                hmma(acc[0][0], ah, bh);
                hmma(acc[0][1], ah, bh + 2);
                hmma(acc[0][2], ah, b2);
                hmma(acc[1][0], ah, bl);
                hmma(acc[1][1], ah, bl + 2);
                hmma(acc[1][2], ah, b2 + 2);
            }
        }
        __syncthreads();
        if (t + NSTAGE < NSTEP && tid == 0) {
            mbar_expect_tx(mb[s], FULLB);
            fill_stage(st, I, SEQ(2 * (t + NSTAGE)), SEQ(2 * (t + NSTAGE) + 1), mb[s]);
        }
    }

    // epilogue: 2-term sum, k-half reduction via smem, single STG
    float sum_[3][4];
    #pragma unroll
    for (int nt = 0; nt < 3; nt++)
        #pragma unroll
        for (int q = 0; q < 4; q++)
            sum_[nt][q] = acc[0][nt][q] + acc[1][nt][q];

    float* red = (float*)smem;
    int row16 = lane >> 2;
    int cb = (lane & 3) * 2;
    if (kh == 1) {
        #pragma unroll
        for (int nt = 0; nt < 3; ++nt) {
            red[(r * 16 + row16) * 26 + nt * 8 + cb]         = sum_[nt][0];
            red[(r * 16 + row16) * 26 + nt * 8 + cb + 1]     = sum_[nt][1];
            red[(r * 16 + row16 + 8) * 26 + nt * 8 + cb]     = sum_[nt][2];
            red[(r * 16 + row16 + 8) * 26 + nt * 8 + cb + 1] = sum_[nt][3];
        }
    }
    __syncthreads();
    if (kh == 0) {
        float* dst = g_part[h];
        int rg0 = I * 64 + r * 16 + row16;
        #pragma unroll
        for (int nt = 0; nt < 3; ++nt) {
            float s0 = sum_[nt][0] + red[(r * 16 + row16) * 26 + nt * 8 + cb];
            float s1 = sum_[nt][1] + red[(r * 16 + row16) * 26 + nt * 8 + cb + 1];
            float s2 = sum_[nt][2] + red[(r * 16 + row16 + 8) * 26 + nt * 8 + cb];
            float s3 = sum_[nt][3] + red[(r * 16 + row16 + 8) * 26 + nt * 8 + cb + 1];
            *(float2*)&dst[(size_t)rg0 * NB + nt * 8 + cb]       = make_float2(s0, s1);
            *(float2*)&dst[(size_t)(rg0 + 8) * NB + nt * 8 + cb] = make_float2(s2, s3);
        }
    }
}

// 144 blocks x 64 threads (full-chip spread), float4 part loads.
__global__ void __launch_bounds__(64) k_combine(const float* __restrict__ mu,
                                                float* __restrict__ out_cm) {
    __shared__ float smu[CC * CC];
    for (int i = threadIdx.x; i < CC * CC; i += 64) smu[i] = mu[i];
    __syncthreads();
    int n = blockIdx.x * 64 + threadIdx.x;   // NPIX = 144*64 exactly
    float m2[NB];
    const float4* p0 = (const float4*)&g_part[0][(size_t)n * NB];
    const float4* p1 = (const float4*)&g_part[1][(size_t)n * NB];
    const float4* p2 = (const float4*)&g_part[2][(size_t)n * NB];
    #pragma unroll
    for (int q = 0; q < 6; q++) {
        float4 a = p0[q], b = p1[q], c = p2[q];
        m2[4*q]     = a.x + b.x + c.x;
        m2[4*q + 1] = a.y + b.y + c.y;
        m2[4*q + 2] = a.z + b.z + c.z;
        m2[4*q + 3] = a.w + b.w + c.w;
    }
    float u[CC];
    float mx = -1e30f;
    #pragma unroll
    for (int c = 0; c < CC; c++) {
        float s = 0.0f;
        #pragma unroll
        for (int c2 = 0; c2 < CC; c2++) s = fmaf(smu[c2 * CC + c], m2[c2], s);
        float v = g_unary[c * NPIX + n] + s;
        g_unary[c * NPIX + n] = v;
        u[c] = v;
        mx = fmaxf(mx, v);
    }
    float s = 0.0f;
    #pragma unroll
    for (int c = 0; c < CC; c++) { u[c] = __expf(u[c] - mx); s += u[c]; }
    write_probs(n, u, 1.0f / s, out_cm);
}

// ---------------- launch ----------------
extern "C" void kernel_launch(void* const* d_in, const int* in_sizes, int n_in,
                              void* d_out, int out_size) {
    const float* x    = (const float*)d_in[0];
    const float* yhat = (const float*)d_in[1];
    const float* mu   = (const float*)d_in[2];
    float* out = (float*)d_out;

    cudaFuncSetAttribute(k_gemm_sym6, cudaFuncAttributeMaxDynamicSharedMemorySize, GEMM_SMEM);

    k_feat<<<(NPIX + 255) / 256, 256>>>(x);
    k_build_t<<<NTILE, 256>>>();
    k_init<<<(NPIX + 255) / 256, 256>>>(yhat, out);

    for (int it = 0; it < CRF_ITERS; ++it) {
        k_gemm_sym6<<<dim3(NBLK, NSPLIT), 256, GEMM_SMEM>>>(it & 1);
        k_combine<<<NBLK, 64>>>(mu, out);
    }
}

// round 14
// speedup vs baseline: 2.3497x; 1.0466x over previous
#include <cuda_runtime.h>
#include <cuda_fp16.h>
#include <cstdint>

#define NPIX 9216
#define HH 96
#define CC 21
#define NB 24
#define CRF_ITERS 5
#define APP_W 10.0f
#define SMO_W 3.0f

#define NBLK 144                        // 64-pixel blocks
#define NTILE (NBLK * (NBLK + 1) / 2)   // 10440 stored upper-tri tiles
#define NSPLIT 3                        // split-K over J-blocks
#define NSTEP 24                        // 48 J-blocks per CTA, 2 per step

// smem stage layout (bytes): 2 A-tiles (hi only) + 2 P-tiles (hi+lo)
#define A0OF 0
#define A1OF 8192
#define P0HI 16384
#define P0LO 19456
#define P1HI 22528
#define P1LO 25600
#define STAGEB 28672
#define NSTAGE 2
#define GEMM_SMEM (NSTAGE * STAGEB)     // 57344
#define FULLB 28672

// XOR swizzle baked into gmem tile layout
#define SW(off) ((off) ^ ((((off) >> 7) & 7) << 4))

// ---------------- persistent device scratch ----------------
static __device__ __half g_Khi[(size_t)NTILE * 4096];  // 85.5 MB, tile-contiguous
static __device__ float  g_feat[6 * NPIX];
static __device__ float  g_gauss[HH];
static __device__ float  g_unary[CC * NPIX];
static __device__ __half g_Bhi[2][NBLK * NB * 64];     // ping-pong P (hi), swizzled
static __device__ __half g_Blo[2][NBLK * NB * 64];     // ping-pong P (lo)
static __device__ float  g_part[NSPLIT][(size_t)NPIX * NB];
static __device__ int    g_ticket[NBLK];               // split-K arrival counters

// ---------------- PTX helpers ----------------
__device__ __forceinline__ uint32_t smem_u32(const void* p) {
    uint32_t a;
    asm("{ .reg .u64 t; cvta.to.shared.u64 t, %1; cvt.u32.u64 %0, t; }" : "=r"(a) : "l"(p));
    return a;
}
__device__ __forceinline__ void mbar_init(uint32_t a, uint32_t c) {
    asm volatile("mbarrier.init.shared.b64 [%0], %1;" :: "r"(a), "r"(c) : "memory");
}
__device__ __forceinline__ void mbar_expect_tx(uint32_t a, uint32_t bytes) {
    asm volatile("mbarrier.arrive.expect_tx.shared.b64 _, [%0], %1;" :: "r"(a), "r"(bytes) : "memory");
}
__device__ __forceinline__ void mbar_wait(uint32_t mbar, uint32_t parity) {
    asm volatile(
        "{\n\t.reg .pred P1;\n\t"
        "WL%=:\n\t"
        "mbarrier.try_wait.parity.shared.b64 P1, [%0], %1;\n\t"
        "@!P1 bra WL%=;\n\t}"
        :: "r"(mbar), "r"(parity) : "memory");
}
__device__ __forceinline__ void bulk_cp(uint32_t dst, const void* src, uint32_t bytes, uint32_t mbar) {
    asm volatile(
        "cp.async.bulk.shared::cluster.global.mbarrier::complete_tx::bytes [%0], [%1], %2, [%3];"
        :: "r"(dst), "l"(src), "r"(bytes), "r"(mbar) : "memory");
}
__device__ __forceinline__ void ldsm4(uint32_t& r0, uint32_t& r1, uint32_t& r2, uint32_t& r3, uint32_t addr) {
    asm volatile("ldmatrix.sync.aligned.m8n8.x4.shared.b16 {%0,%1,%2,%3}, [%4];"
        : "=r"(r0), "=r"(r1), "=r"(r2), "=r"(r3) : "r"(addr));
}
__device__ __forceinline__ void ldsm4t(uint32_t& r0, uint32_t& r1, uint32_t& r2, uint32_t& r3, uint32_t addr) {
    asm volatile("ldmatrix.sync.aligned.m8n8.x4.trans.shared.b16 {%0,%1,%2,%3}, [%4];"
        : "=r"(r0), "=r"(r1), "=r"(r2), "=r"(r3) : "r"(addr));
}
__device__ __forceinline__ void hmma(float* c, const uint32_t* a, const uint32_t* b) {
    asm volatile(
        "mma.sync.aligned.m16n8k16.row.col.f32.f16.f16.f32 "
        "{%0,%1,%2,%3}, {%4,%5,%6,%7}, {%8,%9}, {%0,%1,%2,%3};"
        : "+f"(c[0]), "+f"(c[1]), "+f"(c[2]), "+f"(c[3])
        : "r"(a[0]), "r"(a[1]), "r"(a[2]), "r"(a[3]), "r"(b[0]), "r"(b[1]));
}
__device__ __forceinline__ void tri_decode(int bid, int& lo, int& hi) {
    int r = (int)((sqrtf(8.0f * (float)bid + 1.0f) - 1.0f) * 0.5f);
    while ((r + 1) * (r + 2) / 2 <= bid) ++r;
    while (r * (r + 1) / 2 > bid) --r;
    hi = r;
    lo = bid - r * (r + 1) / 2;
}

// ---------------- kernels ----------------

__global__ void k_feat(const float* __restrict__ x) {
    int n = blockIdx.x * blockDim.x + threadIdx.x;
    if (n >= NPIX) return;
    int y = n / HH, xc = n % HH;
    float f0 = (float)y  * (1.0f / 30.0f);
    float f1 = (float)xc * (1.0f / 30.0f);
    float f2 = x[n]            * 10.0f;
    float f3 = x[NPIX + n]     * 10.0f;
    float f4 = x[2 * NPIX + n] * 10.0f;
    float sq = f0*f0 + f1*f1 + f2*f2 + f3*f3 + f4*f4;
    g_feat[n]            = sq;
    g_feat[NPIX     + n] = f0;
    g_feat[2*NPIX   + n] = f1;
    g_feat[3*NPIX   + n] = f2;
    g_feat[4*NPIX   + n] = f3;
    g_feat[5*NPIX   + n] = f4;
    if (n < HH) g_gauss[n] = expf(-(float)(n * n) * (1.0f / 18.0f));
    if (n < NBLK) g_ticket[n] = 0;
}

// Upper-tri build of K_total = APP_W*K_bi + SMO_W*K_sm into tile-contiguous
// swizzled fp16 layout. K_sm(a,b) = g_gauss[|dy|]*g_gauss[|dx|] (separable table).
__global__ void __launch_bounds__(256) k_build_t() {
    __shared__ float sg[HH];
    int ta, tb;
    tri_decode(blockIdx.x, ta, tb);        // ta <= tb
    size_t tbase = (size_t)blockIdx.x * 8192;
    int tid = threadIdx.x;
    if (tid < HH) sg[tid] = g_gauss[tid];
    __syncthreads();
    int r  = tid >> 2;
    int cq = (tid & 3) * 16;

    int a = ta * 64 + r;
    int ya = a / HH, xa = a % HH;
    float sqa = g_feat[a];
    float a0 = g_feat[NPIX   + a];
    float a1 = g_feat[2*NPIX + a];
    float a2 = g_feat[3*NPIX + a];
    float a3 = g_feat[4*NPIX + a];
    float a4 = g_feat[5*NPIX + a];

    char* Kh = (char*)g_Khi + tbase;
    #pragma unroll
    for (int q = 0; q < 8; ++q) {
        int col = cq + 2 * q;
        int b = tb * 64 + col;
        float2 sqb = *(const float2*)&g_feat[b];
        float2 b0  = *(const float2*)&g_feat[NPIX   + b];
        float2 b1  = *(const float2*)&g_feat[2*NPIX + b];
        float2 b2  = *(const float2*)&g_feat[3*NPIX + b];
        float2 b3  = *(const float2*)&g_feat[4*NPIX + b];
        float2 b4  = *(const float2*)&g_feat[5*NPIX + b];
        float dotx = a0*b0.x + a1*b1.x + a2*b2.x + a3*b3.x + a4*b4.x;
        float doty = a0*b0.y + a1*b1.y + a2*b2.y + a3*b3.y + a4*b4.y;
        int yb0 = b / HH, xb0 = b % HH;
        int yb1 = (b + 1) / HH, xb1 = (b + 1) % HH;
        int dy0 = ya - yb0; dy0 = (dy0 < 0) ? -dy0 : dy0;
        int dx0 = xa - xb0; dx0 = (dx0 < 0) ? -dx0 : dx0;
        int dy1 = ya - yb1; dy1 = (dy1 < 0) ? -dy1 : dy1;
        int dx1 = xa - xb1; dx1 = (dx1 < 0) ? -dx1 : dx1;
        float kx = APP_W * __expf(-0.5f * fmaxf(sqa + sqb.x - 2.0f * dotx, 0.0f))
                 + SMO_W * sg[dy0] * sg[dx0];
        float ky = APP_W * __expf(-0.5f * fmaxf(sqa + sqb.y - 2.0f * doty, 0.0f))
                 + SMO_W * sg[dy1] * sg[dx1];
        uint32_t off = SW((uint32_t)(r * 128 + col * 2));
        *(__half2*)(Kh + off) = __halves2half2(__float2half_rn(kx), __float2half_rn(ky));
    }
}

__device__ __forceinline__ void write_probs(int n, const float* u, float inv,
                                            float* out_cm, int wb) {
    int blk = n >> 6, wi = n & 63;
    char* Bh = (char*)g_Bhi[wb] + (size_t)blk * 3072;
    char* Bl = (char*)g_Blo[wb] + (size_t)blk * 3072;
    #pragma unroll
    for (int c = 0; c < CC; c++) {
        float o = u[c] * inv;
        out_cm[c * NPIX + n] = o;
        __half h = __float2half_rn(o);
        uint32_t off = SW((uint32_t)(c * 128 + wi * 2));
        *(__half*)(Bh + off) = h;
        *(__half*)(Bl + off) = __float2half_rn(o - __half2float(h));
    }
}

__global__ void k_init(const float* __restrict__ yhat, float* __restrict__ out_cm) {
    int n = blockIdx.x * blockDim.x + threadIdx.x;
    if (n >= NPIX) return;
    float u[CC];
    float mx = -1e30f;
    #pragma unroll
    for (int c = 0; c < CC; c++) {
        float v = yhat[c * NPIX + n];
        g_unary[c * NPIX + n] = v;
        u[c] = v;
        mx = fmaxf(mx, v);
    }
    float s = 0.0f;
    #pragma unroll
    for (int c = 0; c < CC; c++) { u[c] = __expf(u[c] - mx); s += u[c]; }
    write_probs(n, u, 1.0f / s, out_cm, 0);
    // zero padded class rows in BOTH buffers (combine never writes them)
    int blk = n >> 6, wi = n & 63;
    #pragma unroll
    for (int b = 0; b < 2; b++) {
        char* Bh = (char*)g_Bhi[b] + (size_t)blk * 3072;
        char* Bl = (char*)g_Blo[b] + (size_t)blk * 3072;
        #pragma unroll
        for (int c = CC; c < NB; c++) {
            uint32_t off = SW((uint32_t)(c * 128 + wi * 2));
            *(__half*)(Bh + off) = __float2half_rn(0.0f);
            *(__half*)(Bl + off) = __float2half_rn(0.0f);
        }
    }
}

// thread-0 stage fill: slot k=0 holds Ja, slot k=1 holds Jb. Reads P buffer pb.
__device__ __forceinline__ void fill_stage(uint32_t st, int I, int Ja, int Jb,
                                           uint32_t mb, int pb) {
    #pragma unroll
    for (int k = 0; k < 2; ++k) {
        int J = (k == 0) ? Ja : Jb;
        int lo = (I < J) ? I : J;
        int hi = (I < J) ? J : I;
        size_t tb2 = (size_t)(hi * (hi + 1) / 2 + lo) * 8192;
        bulk_cp(st + A0OF + k * 8192, (char*)g_Khi + tb2, 8192, mb);
        bulk_cp(st + P0HI + k * 6144, (char*)g_Bhi[pb] + (size_t)J * 3072, 3072, mb);
        bulk_cp(st + P0LO + k * 6144, (char*)g_Blo[pb] + (size_t)J * 3072, 3072, mb);
    }
}

// Owner-computes symmetric GEMM on K_total, 2-term (K*Phi + K*Plo), paired L2
// schedule, 3-way split-K, serpentine J-order, FUSED last-CTA combine+softmax.
// Reads P buffer par, writes P buffer 1-par (race-free within the launch).
__global__ void __launch_bounds__(256, 3) k_gemm_fused(int par,
                                                       const float* __restrict__ mu,
                                                       float* __restrict__ out_cm) {
    extern __shared__ char smem[];
    __shared__ uint64_t mbar_s[NSTAGE];
    __shared__ int s_ticket;
    uint32_t sb = smem_u32(smem);
    int tid = threadIdx.x;
    int lane = tid & 31;
    int w = tid >> 5;
    int r = w & 3;           // 16-row group
    int kh = w >> 2;         // k-half
    int I = blockIdx.x;
    int h = blockIdx.y;
    int Jbase = (48 * h - I + 2 * NBLK) % NBLK;

    #define SEQ(u) ({ int v_ = par ? (2 * NSTEP - 1 - (u)) : (u); \
                      int J_ = Jbase + v_; if (J_ >= NBLK) J_ -= NBLK; J_; })

    uint32_t mb[NSTAGE];
    #pragma unroll
    for (int s = 0; s < NSTAGE; s++) mb[s] = smem_u32(&mbar_s[s]);
    if (tid < NSTAGE) mbar_init(mb[tid], 1);
    __syncthreads();
    if (tid == 0) {
        #pragma unroll
        for (int s = 0; s < NSTAGE; s++) {
            mbar_expect_tx(mb[s], FULLB);
            fill_stage(sb + s * STAGEB, I, SEQ(2 * s), SEQ(2 * s + 1), mb[s], par);
        }
    }

    // --- precomputed swizzled frag offsets ---
    int arow = r * 16 + (lane & 15);
    int ach = (lane >> 4) + kh * 4;
    uint32_t a_sw[2];
    #pragma unroll
    for (int ks = 0; ks < 2; ks++)
        a_sw[ks] = (uint32_t)(arow * 128 + (((ach + ks * 2) ^ (arow & 7)) << 4));
    int gg = lane >> 3;
    int tch = r * 2 + (gg & 1);
    int trow = kh * 32 + (gg >> 1) * 8 + (lane & 7);
    uint32_t t_sw[2];
    #pragma unroll
    for (int ks = 0; ks < 2; ks++)
        t_sw[ks] = (uint32_t)((trow + ks * 16) * 128 + ((tch ^ (lane & 7)) << 4));
    int l2 = lane & 15;
    int brl = l2 & 7;
    int bch = ((l2 >> 3) & 1) + kh * 4;
    uint32_t b4_sw[2], b2p_sw[2];
    #pragma unroll
    for (int ks = 0; ks < 2; ks++) {
        b4_sw[ks]  = (uint32_t)((((lane >> 4) * 8) + brl) * 128 + (((bch + ks * 2) ^ brl) << 4));
        b2p_sw[ks] = (uint32_t)((lane < 16 ? 0 : 3072) + (16 + brl) * 128
                                + (((bch + ks * 2) ^ brl) << 4));
    }

    float acc[2][3][4];
    #pragma unroll
    for (int tm = 0; tm < 2; tm++)
        #pragma unroll
        for (int nt = 0; nt < 3; nt++)
            #pragma unroll
            for (int q = 0; q < 4; q++) acc[tm][nt][q] = 0.0f;

    for (int t = 0; t < NSTEP; ++t) {
        int s = t & 1;
        uint32_t st = sb + s * STAGEB;
        mbar_wait(mb[s], (t >> 1) & 1);

        #pragma unroll
        for (int k = 0; k < 2; ++k) {
            int J = SEQ(2 * t + k);
            uint32_t Ah = st + A0OF + k * 8192;
            uint32_t Ph = st + P0HI + k * 6144;
            #pragma unroll
            for (int ks = 0; ks < 2; ++ks) {
                uint32_t ah[4];
                if (J >= I) ldsm4(ah[0], ah[1], ah[2], ah[3], Ah + a_sw[ks]);
                else        ldsm4t(ah[0], ah[1], ah[2], ah[3], Ah + t_sw[ks]);
                uint32_t bh[4], bl[4], b2[4];
                ldsm4(bh[0], bh[1], bh[2], bh[3], Ph + b4_sw[ks]);
                ldsm4(bl[0], bl[1], bl[2], bl[3], Ph + 3072 + b4_sw[ks]);
                ldsm4(b2[0], b2[1], b2[2], b2[3], Ph + b2p_sw[ks]);
                hmma(acc[0][0], ah, bh);
                hmma(acc[0][1], ah, bh + 2);
                hmma(acc[0][2], ah, b2);
                hmma(acc[1][0], ah, bl);
                hmma(acc[1][1], ah, bl + 2);
                hmma(acc[1][2], ah, b2 + 2);
            }
        }
        __syncthreads();
        if (t + NSTAGE < NSTEP && tid == 0) {
            mbar_expect_tx(mb[s], FULLB);
            fill_stage(st, I, SEQ(2 * (t + NSTAGE)), SEQ(2 * (t + NSTAGE) + 1), mb[s], par);
        }
    }

    // ---- epilogue: 2-term sum, k-half reduction via smem, STG partials ----
    float sum_[3][4];
    #pragma unroll
    for (int nt = 0; nt < 3; nt++)
        #pragma unroll
        for (int q = 0; q < 4; q++)
            sum_[nt][q] = acc[0][nt][q] + acc[1][nt][q];

    float* red = (float*)smem;
    int row16 = lane >> 2;
    int cb = (lane & 3) * 2;
    if (kh == 1) {
        #pragma unroll
        for (int nt = 0; nt < 3; ++nt) {
            red[(r * 16 + row16) * 26 + nt * 8 + cb]         = sum_[nt][0];
            red[(r * 16 + row16) * 26 + nt * 8 + cb + 1]     = sum_[nt][1];
            red[(r * 16 + row16 + 8) * 26 + nt * 8 + cb]     = sum_[nt][2];
            red[(r * 16 + row16 + 8) * 26 + nt * 8 + cb + 1] = sum_[nt][3];
        }
    }
    __syncthreads();
    if (kh == 0) {
        float* dst = g_part[h];
        int rg0 = I * 64 + r * 16 + row16;
        #pragma unroll
        for (int nt = 0; nt < 3; ++nt) {
            float s0 = sum_[nt][0] + red[(r * 16 + row16) * 26 + nt * 8 + cb];
            float s1 = sum_[nt][1] + red[(r * 16 + row16) * 26 + nt * 8 + cb + 1];
            float s2 = sum_[nt][2] + red[(r * 16 + row16 + 8) * 26 + nt * 8 + cb];
            float s3 = sum_[nt][3] + red[(r * 16 + row16 + 8) * 26 + nt * 8 + cb + 1];
            *(float2*)&dst[(size_t)rg0 * NB + nt * 8 + cb]       = make_float2(s0, s1);
            *(float2*)&dst[(size_t)(rg0 + 8) * NB + nt * 8 + cb] = make_float2(s2, s3);
        }
    }

    // ---- fused combine: last of the 3 split-K CTAs finishes block I ----
    __threadfence();
    __syncthreads();
    if (tid == 0) s_ticket = atomicAdd(&g_ticket[I], 1);
    __syncthreads();
    if (s_ticket == NSPLIT - 1) {
        float* smu = (float*)smem;   // red area is dead now
        for (int i = tid; i < CC * CC; i += 256) smu[i] = mu[i];
        __syncthreads();
        if (tid < 64) {
            int n = I * 64 + tid;
            float m2[NB];
            const float4* p0 = (const float4*)&g_part[0][(size_t)n * NB];
            const float4* p1 = (const float4*)&g_part[1][(size_t)n * NB];
            const float4* p2 = (const float4*)&g_part[2][(size_t)n * NB];
            #pragma unroll
            for (int q = 0; q < 6; q++) {
                float4 a = p0[q], b = p1[q], c = p2[q];
                m2[4*q]     = a.x + b.x + c.x;
                m2[4*q + 1] = a.y + b.y + c.y;
                m2[4*q + 2] = a.z + b.z + c.z;
                m2[4*q + 3] = a.w + b.w + c.w;
            }
            float u[CC];
            float mx = -1e30f;
            #pragma unroll
            for (int c = 0; c < CC; c++) {
                float s = 0.0f;
                #pragma unroll
                for (int c2 = 0; c2 < CC; c2++) s = fmaf(smu[c2 * CC + c], m2[c2], s);
                float v = g_unary[c * NPIX + n] + s;
                g_unary[c * NPIX + n] = v;
                u[c] = v;
                mx = fmaxf(mx, v);
            }
            float s = 0.0f;
            #pragma unroll
            for (int c = 0; c < CC; c++) { u[c] = __expf(u[c] - mx); s += u[c]; }
            write_probs(n, u, 1.0f / s, out_cm, 1 - par);   // write OTHER buffer
        }
        if (tid == 0) g_ticket[I] = 0;   // reset for next iteration / replay
    }
}

// ---------------- launch ----------------
extern "C" void kernel_launch(void* const* d_in, const int* in_sizes, int n_in,
                              void* d_out, int out_size) {
    const float* x    = (const float*)d_in[0];
    const float* yhat = (const float*)d_in[1];
    const float* mu   = (const float*)d_in[2];
    float* out = (float*)d_out;

    cudaFuncSetAttribute(k_gemm_fused, cudaFuncAttributeMaxDynamicSharedMemorySize, GEMM_SMEM);

    k_feat<<<(NPIX + 255) / 256, 256>>>(x);
    k_build_t<<<NTILE, 256>>>();
    k_init<<<(NPIX + 255) / 256, 256>>>(yhat, out);

    for (int it = 0; it < CRF_ITERS; ++it)
        k_gemm_fused<<<dim3(NBLK, NSPLIT), 256, GEMM_SMEM>>>(it & 1, mu, out);
}